// round 1
// baseline (speedup 1.0000x reference)
#include <cuda_runtime.h>
#include <math.h>

// ----------------------------------------------------------------------------
// Problem shapes (fixed)
// ----------------------------------------------------------------------------
#define B 4
#define L 2048
#define H 8
#define E 64
#define C (H * E)        // 512
#define L2 (2 * L)       // 4096
#define TOPK 7
#define NSPLIT 4         // column splits for temporal flash kernel

// ----------------------------------------------------------------------------
// Device scratch (no allocations allowed)
// ----------------------------------------------------------------------------
__device__ float g_Mpart[B * NSPLIT * L2];   // partial row max
__device__ float g_Spart[B * NSPLIT * L2];   // partial row expsum (rel. to Mpart)
__device__ float g_instAvg[B * L];           // 0.5*(LSE8(b)+LSE8(4+b)) per (b,t)
__device__ float g_d[B * L];                 // z1[b,t]·z2[b,t]
__device__ float g_corrMean[L];
__device__ int   g_topk[TOPK];

// ----------------------------------------------------------------------------
// Kernel 1: instance-CL part. Per time t: 8x8 gram of {q[0..3,t], k[0..3,t]},
// row-LSE excluding diagonal, plus the paired diagonal dot d[b,t].
// ----------------------------------------------------------------------------
__global__ __launch_bounds__(128) void instance_kernel(const float* __restrict__ Q,
                                                       const float* __restrict__ K) {
    int t = blockIdx.x;
    __shared__ float z[8][C];
    __shared__ float G[8][8];
    __shared__ float lse[8];

    int tid = threadIdx.x;
    for (int idx = tid; idx < 8 * C; idx += 128) {
        int v = idx >> 9;       // vector 0..7
        int c = idx & (C - 1);
        const float* src = (v < 4) ? (Q + ((long)v * L + t) * C)
                                   : (K + ((long)(v - 4) * L + t) * C);
        z[v][c] = src[c];
    }
    __syncthreads();

    if (tid < 64) {
        int i = tid >> 3, j = tid & 7;
        float s = 0.f;
        #pragma unroll 8
        for (int c = 0; c < C; c++) s += z[i][c] * z[j][c];
        G[i][j] = s;
    }
    __syncthreads();

    if (tid < 8) {
        float m = -INFINITY;
        #pragma unroll
        for (int j = 0; j < 8; j++) if (j != tid) m = fmaxf(m, G[tid][j]);
        float s = 0.f;
        #pragma unroll
        for (int j = 0; j < 8; j++) if (j != tid) s += expf(G[tid][j] - m);
        lse[tid] = m + logf(s);
    }
    __syncthreads();

    if (tid < 4) {
        g_instAvg[tid * L + t] = 0.5f * (lse[tid] + lse[tid + 4]);
        g_d[tid * L + t] = G[tid][tid + 4];
    }
}

// ----------------------------------------------------------------------------
// Kernel 2: temporal flash-LSE.  Z_b = concat(q_b, k_b) : (4096, 512).
// Grid (split=4, rowTile=32, b=4). Each CTA: 128 rows x 1024 cols (8 tiles of
// 128), streaming online (max, expsum). FP32, 8x8 register blocking.
// ----------------------------------------------------------------------------
#define BM 128
#define BN 128
#define BK 8

__global__ __launch_bounds__(256) void temporal_flash(const float* __restrict__ Q,
                                                      const float* __restrict__ K) {
    const int split   = blockIdx.x;           // 0..3
    const int rowTile = blockIdx.y;           // 0..31
    const int b       = blockIdx.z;           // 0..3
    const int row0    = rowTile * BM;
    const int col0b   = split * (L2 / NSPLIT);

    __shared__ float As[BK][BM];
    __shared__ float Bs[BK][BN];
    __shared__ float rowM[BM];
    __shared__ float rowS[BM];

    const int tid = threadIdx.x;
    const int tc = tid & 15;     // 0..15 (column group)
    const int tr = tid >> 4;     // 0..15 (row group)

    if (tid < BM) { rowM[tid] = -INFINITY; rowS[tid] = 0.f; }

    const int loadRow = tid >> 1;            // 0..127
    const int loadK4  = (tid & 1) * 4;       // 0 or 4

    const long bbase = (long)b * L * C;
    // row i of Z_b
    const float* Arow = (row0 + loadRow < L)
                            ? (Q + bbase + (long)(row0 + loadRow) * C)
                            : (K + bbase + (long)(row0 + loadRow - L) * C);

    for (int ct = 0; ct < (L2 / NSPLIT) / BN; ct++) {
        const int col0 = col0b + ct * BN;
        const float* Brow = (col0 + loadRow < L)
                                ? (Q + bbase + (long)(col0 + loadRow) * C)
                                : (K + bbase + (long)(col0 + loadRow - L) * C);

        float acc[8][8];
        #pragma unroll
        for (int i = 0; i < 8; i++)
            #pragma unroll
            for (int j = 0; j < 8; j++) acc[i][j] = 0.f;

        for (int k0 = 0; k0 < C; k0 += BK) {
            float4 a4 = *(const float4*)(Arow + k0 + loadK4);
            float4 b4 = *(const float4*)(Brow + k0 + loadK4);
            __syncthreads();
            As[loadK4 + 0][loadRow] = a4.x;
            As[loadK4 + 1][loadRow] = a4.y;
            As[loadK4 + 2][loadRow] = a4.z;
            As[loadK4 + 3][loadRow] = a4.w;
            Bs[loadK4 + 0][loadRow] = b4.x;
            Bs[loadK4 + 1][loadRow] = b4.y;
            Bs[loadK4 + 2][loadRow] = b4.z;
            Bs[loadK4 + 3][loadRow] = b4.w;
            __syncthreads();

            #pragma unroll
            for (int kk = 0; kk < BK; kk++) {
                float4 a0 = *(const float4*)(&As[kk][tr * 8]);
                float4 a1 = *(const float4*)(&As[kk][tr * 8 + 4]);
                float4 b0 = *(const float4*)(&Bs[kk][tc * 8]);
                float4 b1 = *(const float4*)(&Bs[kk][tc * 8 + 4]);
                float av[8] = {a0.x, a0.y, a0.z, a0.w, a1.x, a1.y, a1.z, a1.w};
                float bv[8] = {b0.x, b0.y, b0.z, b0.w, b1.x, b1.y, b1.z, b1.w};
                #pragma unroll
                for (int i = 0; i < 8; i++)
                    #pragma unroll
                    for (int j = 0; j < 8; j++) acc[i][j] = fmaf(av[i], bv[j], acc[i][j]);
            }
        }

        // online LSE epilogue for this 128x128 tile
        const int gr0 = row0 + tr * 8;
        const int gc0 = col0 + tc * 8;
        #pragma unroll
        for (int ii = 0; ii < 8; ii++) {
            const int gr = gr0 + ii;
            float rmax = -INFINITY;
            #pragma unroll
            for (int jj = 0; jj < 8; jj++) {
                if (gc0 + jj == gr) acc[ii][jj] = -INFINITY;  // exclude diagonal
                rmax = fmaxf(rmax, acc[ii][jj]);
            }
            #pragma unroll
            for (int o = 1; o < 16; o <<= 1)
                rmax = fmaxf(rmax, __shfl_xor_sync(0xffffffffu, rmax, o));
            float rsum = 0.f;
            #pragma unroll
            for (int jj = 0; jj < 8; jj++) rsum += __expf(acc[ii][jj] - rmax);
            #pragma unroll
            for (int o = 1; o < 16; o <<= 1)
                rsum += __shfl_xor_sync(0xffffffffu, rsum, o);
            if (tc == 0) {
                const int r = tr * 8 + ii;
                const float mo = rowM[r], so = rowS[r];
                const float mn = fmaxf(mo, rmax);
                rowS[r] = so * __expf(mo - mn) + rsum * __expf(rmax - mn);
                rowM[r] = mn;
            }
        }
    }

    if (tc == 0) {
        #pragma unroll
        for (int ii = 0; ii < 8; ii++) {
            const int r = tr * 8 + ii;
            const int gidx = ((b * NSPLIT + split) * L2) + row0 + r;
            g_Mpart[gidx] = rowM[r];
            g_Spart[gidx] = rowS[r];
        }
    }
}

// ----------------------------------------------------------------------------
// Kernel 3: combine partial LSEs, form corrMean[t].
// ----------------------------------------------------------------------------
__global__ void combine_kernel() {
    int t = blockIdx.x * blockDim.x + threadIdx.x;
    if (t >= L) return;
    float sum = 0.f;
    for (int b = 0; b < B; b++) {
        float lse[2];
        #pragma unroll
        for (int half = 0; half < 2; half++) {
            const int row = t + half * L;
            float M = -INFINITY;
            #pragma unroll
            for (int s = 0; s < NSPLIT; s++)
                M = fmaxf(M, g_Mpart[(b * NSPLIT + s) * L2 + row]);
            float S = 0.f;
            #pragma unroll
            for (int s = 0; s < NSPLIT; s++)
                S += g_Spart[(b * NSPLIT + s) * L2 + row] *
                     expf(g_Mpart[(b * NSPLIT + s) * L2 + row] - M);
            lse[half] = M + logf(S);
        }
        const float tAvg = 0.5f * (lse[0] + lse[1]);
        sum += 0.5f * g_instAvg[b * L + t] + 0.5f * tAvg - g_d[b * L + t];
    }
    g_corrMean[t] = sum * 0.25f;
}

// ----------------------------------------------------------------------------
// Kernel 4: top-7 argmax (single block). Ties -> lowest index (matches lax.top_k).
// ----------------------------------------------------------------------------
__global__ __launch_bounds__(256) void topk_kernel() {
    __shared__ float svals[L];
    __shared__ float bmax[256];
    __shared__ int   bidx[256];
    const int tid = threadIdx.x;
    for (int i = tid; i < L; i += 256) svals[i] = g_corrMean[i];
    __syncthreads();
    for (int k = 0; k < TOPK; k++) {
        float bv = -INFINITY;
        int bi = L;
        for (int i = tid; i < L; i += 256) {
            const float v = svals[i];
            if (v > bv) { bv = v; bi = i; }   // strided ascending -> lowest idx kept
        }
        bmax[tid] = bv; bidx[tid] = bi;
        __syncthreads();
        for (int s = 128; s > 0; s >>= 1) {
            if (tid < s) {
                if (bmax[tid + s] > bmax[tid] ||
                    (bmax[tid + s] == bmax[tid] && bidx[tid + s] < bidx[tid])) {
                    bmax[tid] = bmax[tid + s];
                    bidx[tid] = bidx[tid + s];
                }
            }
            __syncthreads();
        }
        if (tid == 0) { g_topk[k] = bidx[0]; svals[bidx[0]] = -INFINITY; }
        __syncthreads();
    }
}

// ----------------------------------------------------------------------------
// Kernel 5: context = cumsum(V.transpose(0,2,1,3), axis=L); rows at top-7
// indices divided by (index+1). Two-pass chunked scan, coalesced.
// Grid: (h=8, b=4), 512 threads: (chunk=tid/64 in 0..7, e=tid%64).
// ----------------------------------------------------------------------------
__global__ __launch_bounds__(512) void cumsum_kernel(const float* __restrict__ V,
                                                     float* __restrict__ out) {
    const int h = blockIdx.x;
    const int b = blockIdx.y;
    const int tid = threadIdx.x;
    const int e = tid & 63;
    const int chunk = tid >> 6;           // 0..7
    const int LCH = L / 8;                // 256

    __shared__ float csum[8][64];
    __shared__ int idx7[TOPK];
    if (tid < TOPK) idx7[tid] = g_topk[tid];

    // values[b,l,h,e] at b*L*C + l*C + h*E + e
    const long baseIn = (long)b * L * C + (long)h * E + e;
    const int l0 = chunk * LCH;

    float s = 0.f;
    for (int i = 0; i < LCH; i++) s += V[baseIn + (long)(l0 + i) * C];
    csum[chunk][e] = s;
    __syncthreads();

    float off = 0.f;
    for (int c = 0; c < chunk; c++) off += csum[c][e];

    // out[b,h,l,e] at ((b*H+h)*L + l)*E + e
    const long baseOut = ((long)(b * H + h) * L) * E + e;
    float acc = off;
    for (int i = 0; i < LCH; i++) {
        const int l = l0 + i;
        acc += V[baseIn + (long)l * C];
        float o = acc;
        #pragma unroll
        for (int k = 0; k < TOPK; k++)
            if (l == idx7[k]) o = acc / (float)(l + 1);
        out[baseOut + (long)l * E] = o;
    }
}

// ----------------------------------------------------------------------------
// Launch
// ----------------------------------------------------------------------------
extern "C" void kernel_launch(void* const* d_in, const int* in_sizes, int n_in,
                              void* d_out, int out_size) {
    const float* Q = (const float*)d_in[0];
    const float* K = (const float*)d_in[1];
    const float* V = (const float*)d_in[2];
    float* out = (float*)d_out;

    instance_kernel<<<L, 128>>>(Q, K);
    temporal_flash<<<dim3(NSPLIT, L2 / BM, B), 256>>>(Q, K);
    combine_kernel<<<L / 256, 256>>>();
    topk_kernel<<<1, 256>>>();
    cumsum_kernel<<<dim3(H, B), 512>>>(V, out);
}

// round 2
// speedup vs baseline: 1.3485x; 1.3485x over previous
#include <cuda_runtime.h>
#include <math.h>

// ----------------------------------------------------------------------------
// Problem shapes (fixed)
// ----------------------------------------------------------------------------
#define B 4
#define L 2048
#define H 8
#define E 64
#define C (H * E)        // 512
#define L2 (2 * L)       // 4096
#define TOPK 7
#define NTILE 32         // 4096 / 128 row/col tiles
#define NPAIR 528        // NTILE*(NTILE+1)/2 upper-tri pairs

typedef unsigned long long ull;

// ----------------------------------------------------------------------------
// Device scratch (no allocations allowed)
// ----------------------------------------------------------------------------
__device__ float g_Mpart[B * NTILE * L2];    // partial row max, per colTile
__device__ float g_Spart[B * NTILE * L2];    // partial row expsum (rel. to Mpart)
__device__ float g_instAvg[B * L];           // 0.5*(LSE8(b)+LSE8(4+b)) per (b,t)
__device__ float g_d[B * L];                 // z1[b,t]·z2[b,t]
__device__ float g_corrMean[L];
__device__ int   g_topk[TOPK];

// ----------------------------------------------------------------------------
// Packed f32x2 helpers (Blackwell FFMA2 path)
// ----------------------------------------------------------------------------
__device__ __forceinline__ ull fma2(ull a, ull b, ull c) {
    ull d;
    asm("fma.rn.f32x2 %0, %1, %2, %3;" : "=l"(d) : "l"(a), "l"(b), "l"(c));
    return d;
}
__device__ __forceinline__ ull pack2(float a, float b) {
    ull r;
    asm("mov.b64 %0, {%1, %2};" : "=l"(r) : "f"(a), "f"(b));
    return r;
}
__device__ __forceinline__ float2 unpack2(ull v) {
    float2 r;
    asm("mov.b64 {%0, %1}, %2;" : "=f"(r.x), "=f"(r.y) : "l"(v));
    return r;
}

// ----------------------------------------------------------------------------
// Kernel 1: instance-CL part. Per time t: 8x8 gram of {q[0..3,t], k[0..3,t]},
// row-LSE excluding diagonal, plus the paired diagonal dot d[b,t].
// ----------------------------------------------------------------------------
__global__ __launch_bounds__(128) void instance_kernel(const float* __restrict__ Q,
                                                       const float* __restrict__ K) {
    int t = blockIdx.x;
    __shared__ float z[8][C];
    __shared__ float G[8][8];
    __shared__ float lse[8];

    int tid = threadIdx.x;
    for (int idx = tid; idx < 8 * C; idx += 128) {
        int v = idx >> 9;
        int c = idx & (C - 1);
        const float* src = (v < 4) ? (Q + ((long)v * L + t) * C)
                                   : (K + ((long)(v - 4) * L + t) * C);
        z[v][c] = src[c];
    }
    __syncthreads();

    if (tid < 64) {
        int i = tid >> 3, j = tid & 7;
        float s = 0.f;
        #pragma unroll 8
        for (int c = 0; c < C; c++) s += z[i][c] * z[j][c];
        G[i][j] = s;
    }
    __syncthreads();

    if (tid < 8) {
        float m = -INFINITY;
        #pragma unroll
        for (int j = 0; j < 8; j++) if (j != tid) m = fmaxf(m, G[tid][j]);
        float s = 0.f;
        #pragma unroll
        for (int j = 0; j < 8; j++) if (j != tid) s += expf(G[tid][j] - m);
        lse[tid] = m + logf(s);
    }
    __syncthreads();

    if (tid < 4) {
        g_instAvg[tid * L + t] = 0.5f * (lse[tid] + lse[tid + 4]);
        g_d[tid * L + t] = G[tid][tid + 4];
    }
}

// ----------------------------------------------------------------------------
// Kernel 2: symmetric temporal flash-LSE with packed f32x2 FMA.
// Z_b = concat(q_b, k_b) : (4096, 512). Only upper-tri 128x128 tiles (i<=j)
// are computed. Off-diagonal CTAs emit both row-wise (direct) and column-wise
// (transposed) LSE partials. 128 threads, per-thread 8 rows x 16 cols.
// ----------------------------------------------------------------------------
#define BM 128
#define BN 128
#define BK 8

__global__ __launch_bounds__(128) void temporal_sym(const float* __restrict__ Q,
                                                    const float* __restrict__ K) {
    // decode pair index -> (i, j), i <= j
    int p = blockIdx.x;
    int i = 0;
    while (p >= NTILE - i) { p -= NTILE - i; i++; }
    const int j = i + p;
    const int b = blockIdx.y;

    const int row0 = i * BM;
    const int col0 = j * BN;

    __shared__ union {
        struct { float As[BK][BM]; float Bs[BK][BN]; } mm;       // 8 KB
        struct { float partM[16][128]; float colMax[128]; } ep;  // 8.5 KB
    } sm;

    const int tid = threadIdx.x;
    const int tr = tid >> 3;   // 0..15 (row group: 8 rows each)
    const int tc = tid & 7;    // 0..7  (col group: 16 cols each)

    const long bbase = (long)b * L * C;
    const float* Arow = (row0 + tid < L)
                            ? (Q + bbase + (long)(row0 + tid) * C)
                            : (K + bbase + (long)(row0 + tid - L) * C);
    const float* Brow = (col0 + tid < L)
                            ? (Q + bbase + (long)(col0 + tid) * C)
                            : (K + bbase + (long)(col0 + tid - L) * C);

    ull accp[8][8];   // 8 rows x 8 col-pairs (16 cols) packed f32x2
    #pragma unroll
    for (int ii = 0; ii < 8; ii++)
        #pragma unroll
        for (int jj = 0; jj < 8; jj++) accp[ii][jj] = 0ull;

    for (int k0 = 0; k0 < C; k0 += BK) {
        float4 a0 = *(const float4*)(Arow + k0);
        float4 a1 = *(const float4*)(Arow + k0 + 4);
        float4 b0 = *(const float4*)(Brow + k0);
        float4 b1 = *(const float4*)(Brow + k0 + 4);
        __syncthreads();
        sm.mm.As[0][tid] = a0.x; sm.mm.As[1][tid] = a0.y;
        sm.mm.As[2][tid] = a0.z; sm.mm.As[3][tid] = a0.w;
        sm.mm.As[4][tid] = a1.x; sm.mm.As[5][tid] = a1.y;
        sm.mm.As[6][tid] = a1.z; sm.mm.As[7][tid] = a1.w;
        sm.mm.Bs[0][tid] = b0.x; sm.mm.Bs[1][tid] = b0.y;
        sm.mm.Bs[2][tid] = b0.z; sm.mm.Bs[3][tid] = b0.w;
        sm.mm.Bs[4][tid] = b1.x; sm.mm.Bs[5][tid] = b1.y;
        sm.mm.Bs[6][tid] = b1.z; sm.mm.Bs[7][tid] = b1.w;
        __syncthreads();

        #pragma unroll
        for (int kk = 0; kk < BK; kk++) {
            float4 A0 = *(const float4*)(&sm.mm.As[kk][tr * 8]);
            float4 A1 = *(const float4*)(&sm.mm.As[kk][tr * 8 + 4]);
            ulonglong2 Bq0 = *(const ulonglong2*)(&sm.mm.Bs[kk][tc * 16]);
            ulonglong2 Bq1 = *(const ulonglong2*)(&sm.mm.Bs[kk][tc * 16 + 4]);
            ulonglong2 Bq2 = *(const ulonglong2*)(&sm.mm.Bs[kk][tc * 16 + 8]);
            ulonglong2 Bq3 = *(const ulonglong2*)(&sm.mm.Bs[kk][tc * 16 + 12]);
            ull bp[8] = {Bq0.x, Bq0.y, Bq1.x, Bq1.y, Bq2.x, Bq2.y, Bq3.x, Bq3.y};
            float av[8] = {A0.x, A0.y, A0.z, A0.w, A1.x, A1.y, A1.z, A1.w};
            #pragma unroll
            for (int ii = 0; ii < 8; ii++) {
                ull ap = pack2(av[ii], av[ii]);
                #pragma unroll
                for (int jj = 0; jj < 8; jj++)
                    accp[ii][jj] = fma2(ap, bp[jj], accp[ii][jj]);
            }
        }
    }

    // unpack into scalar tile f[8 rows][16 cols]
    float f[8][16];
    #pragma unroll
    for (int ii = 0; ii < 8; ii++)
        #pragma unroll
        for (int jj = 0; jj < 8; jj++) {
            float2 v = unpack2(accp[ii][jj]);
            f[ii][2 * jj] = v.x;
            f[ii][2 * jj + 1] = v.y;
        }

    // ---- direct epilogue: row-wise LSE partial for rows [row0, row0+128) ----
    #pragma unroll
    for (int ii = 0; ii < 8; ii++) {
        const int gr = row0 + tr * 8 + ii;
        float rmax = -INFINITY;
        #pragma unroll
        for (int jj = 0; jj < 16; jj++) {
            if (col0 + tc * 16 + jj == gr) f[ii][jj] = -INFINITY;  // exclude diag
            rmax = fmaxf(rmax, f[ii][jj]);
        }
        rmax = fmaxf(rmax, __shfl_xor_sync(0xffffffffu, rmax, 1));
        rmax = fmaxf(rmax, __shfl_xor_sync(0xffffffffu, rmax, 2));
        rmax = fmaxf(rmax, __shfl_xor_sync(0xffffffffu, rmax, 4));
        float rsum = 0.f;
        #pragma unroll
        for (int jj = 0; jj < 16; jj++) rsum += __expf(f[ii][jj] - rmax);
        rsum += __shfl_xor_sync(0xffffffffu, rsum, 1);
        rsum += __shfl_xor_sync(0xffffffffu, rsum, 2);
        rsum += __shfl_xor_sync(0xffffffffu, rsum, 4);
        if (tc == 0) {
            const int gidx = (b * NTILE + j) * L2 + gr;
            g_Mpart[gidx] = rmax;
            g_Spart[gidx] = rsum;
        }
    }

    // ---- transposed epilogue (i<j): col-wise LSE partial for rows [col0, +128) ----
    if (i != j) {
        __syncthreads();   // main-loop smem reads finished; safe to reuse union
        #pragma unroll
        for (int jj = 0; jj < 16; jj++) {
            float m = f[0][jj];
            #pragma unroll
            for (int ii = 1; ii < 8; ii++) m = fmaxf(m, f[ii][jj]);
            sm.ep.partM[tr][tc * 16 + jj] = m;
        }
        __syncthreads();
        {
            float m = sm.ep.partM[0][tid];
            #pragma unroll
            for (int s = 1; s < 16; s++) m = fmaxf(m, sm.ep.partM[s][tid]);
            sm.ep.colMax[tid] = m;
        }
        __syncthreads();
        float cs[16];
        #pragma unroll
        for (int jj = 0; jj < 16; jj++) {
            const float Mc = sm.ep.colMax[tc * 16 + jj];
            float s = 0.f;
            #pragma unroll
            for (int ii = 0; ii < 8; ii++) s += __expf(f[ii][jj] - Mc);
            cs[jj] = s;
        }
        __syncthreads();   // all partM reads done before overwrite
        #pragma unroll
        for (int jj = 0; jj < 16; jj++) sm.ep.partM[tr][tc * 16 + jj] = cs[jj];
        __syncthreads();
        {
            float s = 0.f;
            #pragma unroll
            for (int t16 = 0; t16 < 16; t16++) s += sm.ep.partM[t16][tid];
            const int gidx = (b * NTILE + i) * L2 + col0 + tid;
            g_Mpart[gidx] = sm.ep.colMax[tid];
            g_Spart[gidx] = s;
        }
    }
}

// ----------------------------------------------------------------------------
// Kernel 3: combine 32 partial LSEs per row, form corrMean[t].
// ----------------------------------------------------------------------------
__global__ void combine_kernel() {
    int t = blockIdx.x * blockDim.x + threadIdx.x;
    if (t >= L) return;
    float sum = 0.f;
    for (int b = 0; b < B; b++) {
        float lse[2];
        #pragma unroll
        for (int half = 0; half < 2; half++) {
            const int row = t + half * L;
            float M = -INFINITY;
            #pragma unroll
            for (int ct = 0; ct < NTILE; ct++)
                M = fmaxf(M, g_Mpart[(b * NTILE + ct) * L2 + row]);
            float S = 0.f;
            #pragma unroll
            for (int ct = 0; ct < NTILE; ct++)
                S += g_Spart[(b * NTILE + ct) * L2 + row] *
                     __expf(g_Mpart[(b * NTILE + ct) * L2 + row] - M);
            lse[half] = M + logf(S);
        }
        const float tAvg = 0.5f * (lse[0] + lse[1]);
        sum += 0.5f * g_instAvg[b * L + t] + 0.5f * tAvg - g_d[b * L + t];
    }
    g_corrMean[t] = sum * 0.25f;
}

// ----------------------------------------------------------------------------
// Kernel 4: top-7 argmax (single block). Ties -> lowest index.
// ----------------------------------------------------------------------------
__global__ __launch_bounds__(256) void topk_kernel() {
    __shared__ float svals[L];
    __shared__ float bmax[256];
    __shared__ int   bidx[256];
    const int tid = threadIdx.x;
    for (int i = tid; i < L; i += 256) svals[i] = g_corrMean[i];
    __syncthreads();
    for (int k = 0; k < TOPK; k++) {
        float bv = -INFINITY;
        int bi = L;
        for (int i = tid; i < L; i += 256) {
            const float v = svals[i];
            if (v > bv) { bv = v; bi = i; }
        }
        bmax[tid] = bv; bidx[tid] = bi;
        __syncthreads();
        for (int s = 128; s > 0; s >>= 1) {
            if (tid < s) {
                if (bmax[tid + s] > bmax[tid] ||
                    (bmax[tid + s] == bmax[tid] && bidx[tid + s] < bidx[tid])) {
                    bmax[tid] = bmax[tid + s];
                    bidx[tid] = bidx[tid + s];
                }
            }
            __syncthreads();
        }
        if (tid == 0) { g_topk[k] = bidx[0]; svals[bidx[0]] = -INFINITY; }
        __syncthreads();
    }
}

// ----------------------------------------------------------------------------
// Kernel 5: context = cumsum(V.transpose(0,2,1,3), axis=L); rows at top-7
// indices divided by (index+1). Two-pass chunked scan, coalesced.
// ----------------------------------------------------------------------------
__global__ __launch_bounds__(512) void cumsum_kernel(const float* __restrict__ V,
                                                     float* __restrict__ out) {
    const int h = blockIdx.x;
    const int b = blockIdx.y;
    const int tid = threadIdx.x;
    const int e = tid & 63;
    const int chunk = tid >> 6;           // 0..7
    const int LCH = L / 8;                // 256

    __shared__ float csum[8][64];
    __shared__ int idx7[TOPK];
    if (tid < TOPK) idx7[tid] = g_topk[tid];

    const long baseIn = (long)b * L * C + (long)h * E + e;
    const int l0 = chunk * LCH;

    float s = 0.f;
    for (int i = 0; i < LCH; i++) s += V[baseIn + (long)(l0 + i) * C];
    csum[chunk][e] = s;
    __syncthreads();

    float off = 0.f;
    for (int c = 0; c < chunk; c++) off += csum[c][e];

    const long baseOut = ((long)(b * H + h) * L) * E + e;
    float acc = off;
    for (int i = 0; i < LCH; i++) {
        const int l = l0 + i;
        acc += V[baseIn + (long)l * C];
        float o = acc;
        #pragma unroll
        for (int k = 0; k < TOPK; k++)
            if (l == idx7[k]) o = acc / (float)(l + 1);
        out[baseOut + (long)l * E] = o;
    }
}

// ----------------------------------------------------------------------------
// Launch
// ----------------------------------------------------------------------------
extern "C" void kernel_launch(void* const* d_in, const int* in_sizes, int n_in,
                              void* d_out, int out_size) {
    const float* Q = (const float*)d_in[0];
    const float* K = (const float*)d_in[1];
    const float* V = (const float*)d_in[2];
    float* out = (float*)d_out;

    instance_kernel<<<L, 128>>>(Q, K);
    temporal_sym<<<dim3(NPAIR, B), 128>>>(Q, K);
    combine_kernel<<<L / 256, 256>>>();
    topk_kernel<<<1, 256>>>();
    cumsum_kernel<<<dim3(H, B), 512>>>(V, out);
}

// round 4
// speedup vs baseline: 3.6973x; 2.7417x over previous
#include <cuda_runtime.h>
#include <cuda_bf16.h>
#include <math.h>
#include <stdint.h>

// ----------------------------------------------------------------------------
// Shapes (fixed)
// ----------------------------------------------------------------------------
#define B 4
#define L 2048
#define H 8
#define E 64
#define C 512
#define L2 4096
#define TOPK 7
#define NTILE 32
#define NPAIR 528
#define NCAND 32

// ----------------------------------------------------------------------------
// Device scratch
// ----------------------------------------------------------------------------
__device__ __nv_bfloat16 g_Zbf[(size_t)B * L2 * C];   // 16 MB bf16 Z = concat(q,k)
__device__ float g_Mpart[B * NTILE * L2];
__device__ float g_Spart[B * NTILE * L2];
__device__ float g_instAvg[B * L];
__device__ float g_d[B * L];
__device__ float g_corrMean[L];
__device__ int   g_cand[NCAND];
__device__ float g_cM[B * 2 * NCAND * 32];
__device__ float g_cS[B * 2 * NCAND * 32];
__device__ int   g_topk[TOPK];

// ----------------------------------------------------------------------------
// Helpers
// ----------------------------------------------------------------------------
#define SWZ(o) ((o) ^ (((o) >> 3) & 0x70))

__device__ __forceinline__ uint32_t smem_u32(const void* p) {
    uint32_t a;
    asm("{ .reg .u64 t; cvta.to.shared.u64 t, %1; cvt.u32.u64 %0, t; }"
        : "=r"(a) : "l"(p));
    return a;
}

#define LDSM4(r0, r1, r2, r3, addr)                                             \
    asm volatile("ldmatrix.sync.aligned.m8n8.x4.shared.b16 {%0,%1,%2,%3}, [%4];" \
                 : "=r"(r0), "=r"(r1), "=r"(r2), "=r"(r3) : "r"(addr))

#define MMA16816(c, a, b0v, b1v)                                                \
    asm volatile("mma.sync.aligned.m16n8k16.row.col.f32.bf16.bf16.f32 "         \
                 "{%0,%1,%2,%3},{%4,%5,%6,%7},{%8,%9},{%0,%1,%2,%3};"           \
                 : "+f"((c)[0]), "+f"((c)[1]), "+f"((c)[2]), "+f"((c)[3])       \
                 : "r"((a)[0]), "r"((a)[1]), "r"((a)[2]), "r"((a)[3]),          \
                   "r"(b0v), "r"(b1v))

// ----------------------------------------------------------------------------
// Kernel 0: convert Q,K fp32 -> bf16 Z (rows: q then k, per batch)
// ----------------------------------------------------------------------------
__global__ __launch_bounds__(256) void convert_kernel(const float* __restrict__ Q,
                                                      const float* __restrict__ K) {
    long t = (long)blockIdx.x * 256 + threadIdx.x;
    long e = t * 8;
    int b = (int)(e / ((long)L2 * C));
    long r = e % ((long)L2 * C);
    int row = (int)(r / C);
    int k = (int)(r % C);
    const float* src = (row < L) ? Q + ((long)b * L + row) * C + k
                                 : K + ((long)b * L + (row - L)) * C + k;
    float4 f0 = *(const float4*)(src);
    float4 f1 = *(const float4*)(src + 4);
    __nv_bfloat162 h0 = __float22bfloat162_rn(make_float2(f0.x, f0.y));
    __nv_bfloat162 h1 = __float22bfloat162_rn(make_float2(f0.z, f0.w));
    __nv_bfloat162 h2 = __float22bfloat162_rn(make_float2(f1.x, f1.y));
    __nv_bfloat162 h3 = __float22bfloat162_rn(make_float2(f1.z, f1.w));
    uint4 o;
    o.x = *(uint32_t*)&h0; o.y = *(uint32_t*)&h1;
    o.z = *(uint32_t*)&h2; o.w = *(uint32_t*)&h3;
    *(uint4*)(g_Zbf + e) = o;
}

// ----------------------------------------------------------------------------
// Kernel 1: instance-CL (exact fp32)
// ----------------------------------------------------------------------------
__global__ __launch_bounds__(128) void instance_kernel(const float* __restrict__ Q,
                                                       const float* __restrict__ K) {
    int t = blockIdx.x;
    __shared__ float z[8][C];
    __shared__ float G[8][8];
    __shared__ float lse[8];
    int tid = threadIdx.x;
    for (int idx = tid; idx < 8 * C; idx += 128) {
        int v = idx >> 9, c = idx & (C - 1);
        const float* src = (v < 4) ? (Q + ((long)v * L + t) * C)
                                   : (K + ((long)(v - 4) * L + t) * C);
        z[v][c] = src[c];
    }
    __syncthreads();
    if (tid < 64) {
        int i = tid >> 3, j = tid & 7;
        float s = 0.f;
        #pragma unroll 8
        for (int c = 0; c < C; c++) s += z[i][c] * z[j][c];
        G[i][j] = s;
    }
    __syncthreads();
    if (tid < 8) {
        float m = -INFINITY;
        #pragma unroll
        for (int j = 0; j < 8; j++) if (j != tid) m = fmaxf(m, G[tid][j]);
        float s = 0.f;
        #pragma unroll
        for (int j = 0; j < 8; j++) if (j != tid) s += expf(G[tid][j] - m);
        lse[tid] = m + logf(s);
    }
    __syncthreads();
    if (tid < 4) {
        g_instAvg[tid * L + t] = 0.5f * (lse[tid] + lse[tid + 4]);
        g_d[tid * L + t] = G[tid][tid + 4];
    }
}

// ----------------------------------------------------------------------------
// Kernel 2: symmetric temporal gram via mma.sync bf16 (HMMA) + LSE epilogue.
// CTA = (pair (i<=j), batch). 256 thr = 8 warps; warp tile 32x64
// (wr = wid>>1 row group, wc = wid&1 col half). K staged in 64-wide chunks.
// ----------------------------------------------------------------------------
__global__ __launch_bounds__(256) void temporal_mma() {
    int p = blockIdx.x;
    int i = 0;
    while (p >= NTILE - i) { p -= NTILE - i; i++; }
    const int j = i + p;
    const int b = blockIdx.y;

    __shared__ __align__(1024) __nv_bfloat16 As[128 * 64];
    __shared__ __align__(1024) __nv_bfloat16 Bs[128 * 64];
    __shared__ float rmW[2][128], smW[2][128];
    __shared__ float cmW[4][128], csW[4][128];

    const int tid = threadIdx.x;
    const int wid = tid >> 5, ln = tid & 31;
    const int wr = wid >> 1, wc = wid & 1;
    const int qr = ln >> 2, qc = ln & 3;

    const __nv_bfloat16* Zb = g_Zbf + (size_t)b * L2 * C;
    const __nv_bfloat16* Arows = Zb + (size_t)i * 128 * C;
    const __nv_bfloat16* Brows = Zb + (size_t)j * 128 * C;

    const uint32_t aBase = smem_u32(As);
    const uint32_t bBase = smem_u32(Bs);

    float acc[2][8][4];
    #pragma unroll
    for (int mt = 0; mt < 2; mt++)
        #pragma unroll
        for (int nt = 0; nt < 8; nt++)
            #pragma unroll
            for (int q = 0; q < 4; q++) acc[mt][nt][q] = 0.f;

    const int blk = ln >> 3, r8 = ln & 7;

    for (int ck = 0; ck < 8; ck++) {
        __syncthreads();
        #pragma unroll
        for (int u = 0; u < 4; u++) {
            int unit = tid + u * 256;
            int row = unit >> 3, seg = unit & 7;
            uint32_t off = SWZ(row * 128 + seg * 16);
            *(uint4*)((char*)As + off) = *(const uint4*)(Arows + (size_t)row * C + ck * 64 + seg * 8);
            *(uint4*)((char*)Bs + off) = *(const uint4*)(Brows + (size_t)row * C + ck * 64 + seg * 8);
        }
        __syncthreads();

        #pragma unroll
        for (int ks = 0; ks < 4; ks++) {
            uint32_t af[2][4];
            #pragma unroll
            for (int mt = 0; mt < 2; mt++) {
                int row = wr * 32 + mt * 16 + (blk & 1) * 8 + r8;
                int unit = ks * 2 + (blk >> 1);
                LDSM4(af[mt][0], af[mt][1], af[mt][2], af[mt][3],
                      aBase + SWZ(row * 128 + unit * 16));
            }
            uint32_t bf[4][4];
            #pragma unroll
            for (int nn = 0; nn < 4; nn++) {
                int row = wc * 64 + nn * 16 + (blk >> 1) * 8 + r8;
                int unit = ks * 2 + (blk & 1);
                LDSM4(bf[nn][0], bf[nn][1], bf[nn][2], bf[nn][3],
                      bBase + SWZ(row * 128 + unit * 16));
            }
            #pragma unroll
            for (int mt = 0; mt < 2; mt++)
                #pragma unroll
                for (int nn = 0; nn < 4; nn++) {
                    MMA16816(acc[mt][2 * nn], af[mt], bf[nn][0], bf[nn][1]);
                    MMA16816(acc[mt][2 * nn + 1], af[mt], bf[nn][2], bf[nn][3]);
                }
        }
    }

    // diagonal exclusion (only diag tile)
    if (i == j) {
        #pragma unroll
        for (int mt = 0; mt < 2; mt++)
            #pragma unroll
            for (int nt = 0; nt < 8; nt++)
                #pragma unroll
                for (int h = 0; h < 2; h++)
                    #pragma unroll
                    for (int q = 0; q < 2; q++) {
                        int rI = wr * 32 + mt * 16 + h * 8 + qr;
                        int cI = wc * 64 + nt * 8 + qc * 2 + q;
                        if (rI == cI) acc[mt][nt][h * 2 + q] = -INFINITY;
                    }
    }

    // ---- row-side LSE partials (slot j) ----
    #pragma unroll
    for (int mt = 0; mt < 2; mt++)
        #pragma unroll
        for (int h = 0; h < 2; h++) {
            float m = -INFINITY;
            #pragma unroll
            for (int nt = 0; nt < 8; nt++)
                m = fmaxf(m, fmaxf(acc[mt][nt][h * 2], acc[mt][nt][h * 2 + 1]));
            m = fmaxf(m, __shfl_xor_sync(0xffffffffu, m, 1));
            m = fmaxf(m, __shfl_xor_sync(0xffffffffu, m, 2));
            if (qc == 0) rmW[wc][wr * 32 + mt * 16 + h * 8 + qr] = m;
        }
    __syncthreads();
    #pragma unroll
    for (int mt = 0; mt < 2; mt++)
        #pragma unroll
        for (int h = 0; h < 2; h++) {
            int r = wr * 32 + mt * 16 + h * 8 + qr;
            float Mf = fmaxf(rmW[0][r], rmW[1][r]);
            float thr = Mf - 17.0f;
            float s = 0.f;
            #pragma unroll
            for (int nt = 0; nt < 8; nt++)
                #pragma unroll
                for (int q = 0; q < 2; q++) {
                    float v = acc[mt][nt][h * 2 + q];
                    if (v > thr) s += __expf(v - Mf);
                }
            s += __shfl_xor_sync(0xffffffffu, s, 1);
            s += __shfl_xor_sync(0xffffffffu, s, 2);
            if (qc == 0) smW[wc][r] = s;
        }
    __syncthreads();
    if (tid < 128) {
        float Mf = fmaxf(rmW[0][tid], rmW[1][tid]);
        float S = smW[0][tid] + smW[1][tid];
        int gi = (b * NTILE + j) * L2 + i * 128 + tid;
        g_Mpart[gi] = Mf;
        g_Spart[gi] = S;
    }

    // ---- col-side LSE partials (slot i), only off-diagonal ----
    if (i != j) {
        #pragma unroll
        for (int nt = 0; nt < 8; nt++)
            #pragma unroll
            for (int q = 0; q < 2; q++) {
                float m = -INFINITY;
                #pragma unroll
                for (int mt = 0; mt < 2; mt++)
                    #pragma unroll
                    for (int h = 0; h < 2; h++)
                        m = fmaxf(m, acc[mt][nt][h * 2 + q]);
                m = fmaxf(m, __shfl_xor_sync(0xffffffffu, m, 4));
                m = fmaxf(m, __shfl_xor_sync(0xffffffffu, m, 8));
                m = fmaxf(m, __shfl_xor_sync(0xffffffffu, m, 16));
                if (qr == 0) cmW[wr][wc * 64 + nt * 8 + qc * 2 + q] = m;
            }
        __syncthreads();
        #pragma unroll
        for (int nt = 0; nt < 8; nt++)
            #pragma unroll
            for (int q = 0; q < 2; q++) {
                int cI = wc * 64 + nt * 8 + qc * 2 + q;
                float Mf = fmaxf(fmaxf(cmW[0][cI], cmW[1][cI]),
                                 fmaxf(cmW[2][cI], cmW[3][cI]));
                float thr = Mf - 17.0f;
                float s = 0.f;
                #pragma unroll
                for (int mt = 0; mt < 2; mt++)
                    #pragma unroll
                    for (int h = 0; h < 2; h++) {
                        float v = acc[mt][nt][h * 2 + q];
                        if (v > thr) s += __expf(v - Mf);
                    }
                s += __shfl_xor_sync(0xffffffffu, s, 4);
                s += __shfl_xor_sync(0xffffffffu, s, 8);
                s += __shfl_xor_sync(0xffffffffu, s, 16);
                if (qr == 0) csW[wr][cI] = s;
            }
        __syncthreads();
        if (tid < 128) {
            float Mf = fmaxf(fmaxf(cmW[0][tid], cmW[1][tid]),
                             fmaxf(cmW[2][tid], cmW[3][tid]));
            float S = csW[0][tid] + csW[1][tid] + csW[2][tid] + csW[3][tid];
            int gi = (b * NTILE + i) * L2 + j * 128 + tid;
            g_Mpart[gi] = Mf;
            g_Spart[gi] = S;
        }
    }
}

// ----------------------------------------------------------------------------
// Kernel 3: combine 32 partials per row -> approx corrMean
// ----------------------------------------------------------------------------
__global__ void combine_kernel() {
    int t = blockIdx.x * blockDim.x + threadIdx.x;
    if (t >= L) return;
    float sum = 0.f;
    for (int b = 0; b < B; b++) {
        float lse[2];
        #pragma unroll
        for (int hh = 0; hh < 2; hh++) {
            const int row = t + hh * L;
            float M = -INFINITY;
            #pragma unroll
            for (int ct = 0; ct < NTILE; ct++)
                M = fmaxf(M, g_Mpart[(b * NTILE + ct) * L2 + row]);
            float S = 0.f;
            #pragma unroll
            for (int ct = 0; ct < NTILE; ct++)
                S += g_Spart[(b * NTILE + ct) * L2 + row] *
                     __expf(g_Mpart[(b * NTILE + ct) * L2 + row] - M);
            lse[hh] = M + logf(S);
        }
        const float tAvg = 0.5f * (lse[0] + lse[1]);
        sum += 0.5f * g_instAvg[b * L + t] + 0.5f * tAvg - g_d[b * L + t];
    }
    g_corrMean[t] = sum * 0.25f;
}

// ----------------------------------------------------------------------------
// Kernel 4: top-32 candidate extraction (single warp, register-resident).
// Lexicographic-next enumeration (val desc, idx asc), no removal.
// ----------------------------------------------------------------------------
__global__ __launch_bounds__(32) void cand_kernel() {
    const int ln = threadIdx.x;
    float v[64];
    #pragma unroll
    for (int u = 0; u < 64; u++) v[u] = g_corrMean[u * 32 + ln];
    float pv = INFINITY;
    int pi = -1;
    for (int r = 0; r < NCAND; r++) {
        float bv = -INFINITY;
        int bi = 1 << 30;
        #pragma unroll
        for (int u = 0; u < 64; u++) {
            int idx = u * 32 + ln;
            bool lt = (v[u] < pv) || (v[u] == pv && idx > pi);
            if (lt && (v[u] > bv || (v[u] == bv && idx < bi))) { bv = v[u]; bi = idx; }
        }
        #pragma unroll
        for (int o = 16; o > 0; o >>= 1) {
            float ov = __shfl_xor_sync(0xffffffffu, bv, o);
            int oi = __shfl_xor_sync(0xffffffffu, bi, o);
            if (ov > bv || (ov == bv && oi < bi)) { bv = ov; bi = oi; }
        }
        if (ln == 0) g_cand[r] = bi;
        pv = bv; pi = bi;
    }
}

// ----------------------------------------------------------------------------
// Kernel 5: exact fp32 rescreen of candidates. Grid (32 col-blocks, B).
// Computes partial (max, expsum) of temporal rows {cand, cand+L} over this
// block's 128 Z-cols, exactly in fp32 from Q/K.
// ----------------------------------------------------------------------------
__global__ __launch_bounds__(256) void rescreen(const float* __restrict__ Q,
                                                const float* __restrict__ K) {
    const int blk = blockIdx.x, b = blockIdx.y;
    __shared__ float czT[32][64];
    __shared__ float colT[32][128];
    __shared__ float pr[16][64];
    __shared__ float Mrow[64];
    __shared__ int cand[NCAND];

    const int tid = threadIdx.x;
    const int tcg = tid >> 4, tcol = tid & 15;
    if (tid < NCAND) cand[tid] = g_cand[tid];
    __syncthreads();

    float sc[4][8];
    #pragma unroll
    for (int cc = 0; cc < 4; cc++)
        #pragma unroll
        for (int w = 0; w < 8; w++) sc[cc][w] = 0.f;

    for (int ck = 0; ck < 16; ck++) {
        __syncthreads();
        for (int idx = tid; idx < 64 * 32; idx += 256) {
            int r = idx >> 5, kk = idx & 31;
            int c = r >> 1, h = r & 1;
            int t = cand[c];
            const float* src = h ? (K + ((size_t)b * L + t) * C)
                                 : (Q + ((size_t)b * L + t) * C);
            czT[kk][r] = src[ck * 32 + kk];
        }
        for (int idx = tid; idx < 128 * 32; idx += 256) {
            int r = idx >> 5, kk = idx & 31;
            int gid = blk * 128 + r;
            const float* src = (gid < L) ? (Q + ((size_t)b * L + gid) * C)
                                         : (K + ((size_t)b * L + gid - L) * C);
            colT[kk][r] = src[ck * 32 + kk];
        }
        __syncthreads();
        #pragma unroll 4
        for (int kk = 0; kk < 32; kk++) {
            float a0 = czT[kk][tcg], a1 = czT[kk][tcg + 16];
            float a2 = czT[kk][tcg + 32], a3 = czT[kk][tcg + 48];
            float bv[8];
            #pragma unroll
            for (int w = 0; w < 8; w++) bv[w] = colT[kk][tcol + 16 * w];
            #pragma unroll
            for (int w = 0; w < 8; w++) {
                sc[0][w] = fmaf(a0, bv[w], sc[0][w]);
                sc[1][w] = fmaf(a1, bv[w], sc[1][w]);
                sc[2][w] = fmaf(a2, bv[w], sc[2][w]);
                sc[3][w] = fmaf(a3, bv[w], sc[3][w]);
            }
        }
    }

    // diag exclusion
    #pragma unroll
    for (int cc = 0; cc < 4; cc++) {
        int ci = tcg + 16 * cc;
        int rowid = cand[ci >> 1] + (ci & 1) * L;
        #pragma unroll
        for (int w = 0; w < 8; w++) {
            int gid = blk * 128 + tcol + 16 * w;
            if (gid == rowid) sc[cc][w] = -INFINITY;
        }
    }

    __syncthreads();
    #pragma unroll
    for (int cc = 0; cc < 4; cc++) {
        int ci = tcg + 16 * cc;
        float m = sc[cc][0];
        #pragma unroll
        for (int w = 1; w < 8; w++) m = fmaxf(m, sc[cc][w]);
        pr[tcol][ci] = m;
    }
    __syncthreads();
    if (tid < 64) {
        float m = pr[0][tid];
        #pragma unroll
        for (int x = 1; x < 16; x++) m = fmaxf(m, pr[x][tid]);
        Mrow[tid] = m;
    }
    __syncthreads();
    #pragma unroll
    for (int cc = 0; cc < 4; cc++) {
        int ci = tcg + 16 * cc;
        float Mf = Mrow[ci];
        float s = 0.f;
        #pragma unroll
        for (int w = 0; w < 8; w++) s += __expf(sc[cc][w] - Mf);
        pr[tcol][ci] = s;
    }
    __syncthreads();
    if (tid < 64) {
        float s = 0.f;
        #pragma unroll
        for (int x = 0; x < 16; x++) s += pr[x][tid];
        int gi = (b * 64 + tid) * 32 + blk;
        g_cM[gi] = Mrow[tid];
        g_cS[gi] = s;
    }
}

// ----------------------------------------------------------------------------
// Kernel 6: final exact top-7 among candidates.
// ----------------------------------------------------------------------------
__global__ __launch_bounds__(64) void final_topk() {
    __shared__ float ls[B][64];
    __shared__ float val[NCAND];
    const int tid = threadIdx.x;
    if (tid < 64) {
        for (int b = 0; b < B; b++) {
            float M = -INFINITY;
            #pragma unroll
            for (int blk = 0; blk < 32; blk++)
                M = fmaxf(M, g_cM[(b * 64 + tid) * 32 + blk]);
            float S = 0.f;
            #pragma unroll
            for (int blk = 0; blk < 32; blk++)
                S += g_cS[(b * 64 + tid) * 32 + blk] *
                     __expf(g_cM[(b * 64 + tid) * 32 + blk] - M);
            ls[b][tid] = M + logf(S);
        }
    }
    __syncthreads();
    if (tid < NCAND) {
        int t = g_cand[tid];
        float sum = 0.f;
        for (int b = 0; b < B; b++) {
            float tavg = 0.5f * (ls[b][2 * tid] + ls[b][2 * tid + 1]);
            sum += 0.5f * g_instAvg[b * L + t] + 0.5f * tavg - g_d[b * L + t];
        }
        val[tid] = sum * 0.25f;
    }
    __syncthreads();
    if (tid == 0) {
        unsigned used = 0;
        for (int k = 0; k < TOPK; k++) {
            float best = -INFINITY;
            int bc = -1, bt = 1 << 30;
            for (int c = 0; c < NCAND; c++) {
                if ((used >> c) & 1) continue;
                int t = g_cand[c];
                if (val[c] > best || (val[c] == best && t < bt)) {
                    best = val[c]; bc = c; bt = t;
                }
            }
            used |= 1u << bc;
            g_topk[k] = g_cand[bc];
        }
    }
}

// ----------------------------------------------------------------------------
// Kernel 7: cumsum of V with top-7 rows rescaled
// ----------------------------------------------------------------------------
__global__ __launch_bounds__(512) void cumsum_kernel(const float* __restrict__ V,
                                                     float* __restrict__ out) {
    const int h = blockIdx.x;
    const int b = blockIdx.y;
    const int tid = threadIdx.x;
    const int e = tid & 63;
    const int chunk = tid >> 6;
    const int LCH = L / 8;

    __shared__ float csum[8][64];
    __shared__ int idx7[TOPK];
    if (tid < TOPK) idx7[tid] = g_topk[tid];

    const long baseIn = (long)b * L * C + (long)h * E + e;
    const int l0 = chunk * LCH;

    float s = 0.f;
    for (int i = 0; i < LCH; i++) s += V[baseIn + (long)(l0 + i) * C];
    csum[chunk][e] = s;
    __syncthreads();

    float off = 0.f;
    for (int c = 0; c < chunk; c++) off += csum[c][e];

    const long baseOut = ((long)(b * H + h) * L) * E + e;
    float acc = off;
    for (int i = 0; i < LCH; i++) {
        const int l = l0 + i;
        acc += V[baseIn + (long)l * C];
        float o = acc;
        #pragma unroll
        for (int k = 0; k < TOPK; k++)
            if (l == idx7[k]) o = acc / (float)(l + 1);
        out[baseOut + (long)l * E] = o;
    }
}

// ----------------------------------------------------------------------------
// Launch
// ----------------------------------------------------------------------------
extern "C" void kernel_launch(void* const* d_in, const int* in_sizes, int n_in,
                              void* d_out, int out_size) {
    const float* Q = (const float*)d_in[0];
    const float* K = (const float*)d_in[1];
    const float* V = (const float*)d_in[2];
    float* out = (float*)d_out;

    convert_kernel<<<(B * L2 * C) / 8 / 256, 256>>>(Q, K);
    instance_kernel<<<L, 128>>>(Q, K);
    temporal_mma<<<dim3(NPAIR, B), 256>>>();
    combine_kernel<<<L / 256, 256>>>();
    cand_kernel<<<1, 32>>>();
    rescreen<<<dim3(32, B), 256>>>(Q, K);
    final_topk<<<1, 64>>>();
    cumsum_kernel<<<dim3(H, B), 512>>>(V, out);
}

// round 5
// speedup vs baseline: 4.5817x; 1.2392x over previous
#include <cuda_runtime.h>
#include <cuda_bf16.h>
#include <math.h>
#include <stdint.h>

// ----------------------------------------------------------------------------
// Shapes (fixed)
// ----------------------------------------------------------------------------
#define B 4
#define L 2048
#define H 8
#define E 64
#define C 512
#define L2 4096
#define TOPK 7
#define NTILE 32
#define NPAIR 528
#define NCAND 32

// ----------------------------------------------------------------------------
// Device scratch
// ----------------------------------------------------------------------------
__device__ __nv_bfloat16 g_Zbf[(size_t)B * L2 * C];   // 16 MB bf16 Z = concat(q,k)
__device__ float g_Mpart[B * NTILE * L2];
__device__ float g_Spart[B * NTILE * L2];
__device__ float g_instAvg[B * L];
__device__ float g_d[B * L];
__device__ float g_corrPart[B * L];                   // per-batch corr partial
__device__ int   g_cand[NCAND];
__device__ float g_cM[B * 2 * NCAND * 32];
__device__ float g_cS[B * 2 * NCAND * 32];
__device__ int   g_topk[TOPK];
__device__ float g_csum[B * H * 32 * E];              // chunk sums for cumsum

// ----------------------------------------------------------------------------
// Helpers
// ----------------------------------------------------------------------------
#define SWZ(o) ((o) ^ (((o) >> 3) & 0x70))

__device__ __forceinline__ uint32_t smem_u32(const void* p) {
    uint32_t a;
    asm("{ .reg .u64 t; cvta.to.shared.u64 t, %1; cvt.u32.u64 %0, t; }"
        : "=r"(a) : "l"(p));
    return a;
}

#define LDSM4(r0, r1, r2, r3, addr)                                             \
    asm volatile("ldmatrix.sync.aligned.m8n8.x4.shared.b16 {%0,%1,%2,%3}, [%4];" \
                 : "=r"(r0), "=r"(r1), "=r"(r2), "=r"(r3) : "r"(addr))

#define MMA16816(c, a, b0v, b1v)                                                \
    asm volatile("mma.sync.aligned.m16n8k16.row.col.f32.bf16.bf16.f32 "         \
                 "{%0,%1,%2,%3},{%4,%5,%6,%7},{%8,%9},{%0,%1,%2,%3};"           \
                 : "+f"((c)[0]), "+f"((c)[1]), "+f"((c)[2]), "+f"((c)[3])       \
                 : "r"((a)[0]), "r"((a)[1]), "r"((a)[2]), "r"((a)[3]),          \
                   "r"(b0v), "r"(b1v))

#define CPASYNC16(dst, src)                                                     \
    asm volatile("cp.async.cg.shared.global [%0], [%1], 16;"                    \
                 :: "r"(dst), "l"(src) : "memory")
#define CPCOMMIT() asm volatile("cp.async.commit_group;" ::: "memory")
#define CPWAIT(n)  asm volatile("cp.async.wait_group %0;" :: "n"(n) : "memory")

// ----------------------------------------------------------------------------
// Kernel 0: convert Q,K fp32 -> bf16 Z (rows: q then k, per batch)
// ----------------------------------------------------------------------------
__global__ __launch_bounds__(256) void convert_kernel(const float* __restrict__ Q,
                                                      const float* __restrict__ K) {
    long t = (long)blockIdx.x * 256 + threadIdx.x;
    long e = t * 8;
    int b = (int)(e / ((long)L2 * C));
    long r = e % ((long)L2 * C);
    int row = (int)(r / C);
    int k = (int)(r % C);
    const float* src = (row < L) ? Q + ((long)b * L + row) * C + k
                                 : K + ((long)b * L + (row - L)) * C + k;
    float4 f0 = *(const float4*)(src);
    float4 f1 = *(const float4*)(src + 4);
    __nv_bfloat162 h0 = __float22bfloat162_rn(make_float2(f0.x, f0.y));
    __nv_bfloat162 h1 = __float22bfloat162_rn(make_float2(f0.z, f0.w));
    __nv_bfloat162 h2 = __float22bfloat162_rn(make_float2(f1.x, f1.y));
    __nv_bfloat162 h3 = __float22bfloat162_rn(make_float2(f1.z, f1.w));
    uint4 o;
    o.x = *(uint32_t*)&h0; o.y = *(uint32_t*)&h1;
    o.z = *(uint32_t*)&h2; o.w = *(uint32_t*)&h3;
    *(uint4*)(g_Zbf + e) = o;
}

// ----------------------------------------------------------------------------
// Kernel 1: instance-CL (exact fp32)
// ----------------------------------------------------------------------------
__global__ __launch_bounds__(128) void instance_kernel(const float* __restrict__ Q,
                                                       const float* __restrict__ K) {
    int t = blockIdx.x;
    __shared__ float z[8][C];
    __shared__ float G[8][8];
    __shared__ float lse[8];
    int tid = threadIdx.x;
    for (int idx = tid; idx < 8 * C; idx += 128) {
        int v = idx >> 9, c = idx & (C - 1);
        const float* src = (v < 4) ? (Q + ((long)v * L + t) * C)
                                   : (K + ((long)(v - 4) * L + t) * C);
        z[v][c] = src[c];
    }
    __syncthreads();
    if (tid < 64) {
        int i = tid >> 3, j = tid & 7;
        float s = 0.f;
        #pragma unroll 8
        for (int c = 0; c < C; c++) s += z[i][c] * z[j][c];
        G[i][j] = s;
    }
    __syncthreads();
    if (tid < 8) {
        float m = -INFINITY;
        #pragma unroll
        for (int j = 0; j < 8; j++) if (j != tid) m = fmaxf(m, G[tid][j]);
        float s = 0.f;
        #pragma unroll
        for (int j = 0; j < 8; j++) if (j != tid) s += expf(G[tid][j] - m);
        lse[tid] = m + logf(s);
    }
    __syncthreads();
    if (tid < 4) {
        g_instAvg[tid * L + t] = 0.5f * (lse[tid] + lse[tid + 4]);
        g_d[tid * L + t] = G[tid][tid + 4];
    }
}

// ----------------------------------------------------------------------------
// Kernel 2: symmetric temporal gram via mma.sync bf16 + cp.async pipeline.
// CTA = (pair (i<=j), batch). 256 thr = 8 warps; warp tile 32x64.
// Dynamic smem: As[2][128x64] | Bs[2][128x64] (64 KB), double-buffered.
// Epilogue arrays reuse the tile smem after the mainloop.
// ----------------------------------------------------------------------------
__global__ __launch_bounds__(256, 2) void temporal_mma() {
    int p = blockIdx.x;
    int i = 0;
    while (p >= NTILE - i) { p -= NTILE - i; i++; }
    const int j = i + p;
    const int b = blockIdx.y;

    extern __shared__ __align__(1024) char dsm[];
    const uint32_t aBase = smem_u32(dsm);            // As[2]: 32 KB
    const uint32_t bBase = aBase + 32768;            // Bs[2]: 32 KB
    float* rmW = (float*)dsm;                        // reuse post-mainloop
    float* smW = rmW + 256;
    float* cmW = smW + 256;
    float* csW = cmW + 512;

    const int tid = threadIdx.x;
    const int wid = tid >> 5, ln = tid & 31;
    const int wr = wid >> 1, wc = wid & 1;
    const int qr = ln >> 2, qc = ln & 3;

    const __nv_bfloat16* Zb = g_Zbf + (size_t)b * L2 * C;
    const __nv_bfloat16* Arows = Zb + (size_t)i * 128 * C;
    const __nv_bfloat16* Brows = Zb + (size_t)j * 128 * C;

    // per-thread load slots: 4 units of 16B per array per chunk
    const int ldRow[4] = {(tid + 0) >> 3, (tid + 256) >> 3,
                          (tid + 512) >> 3, (tid + 768) >> 3};
    const int ldSeg = tid & 7;
    const uint32_t ldOff[4] = {
        (uint32_t)SWZ(ldRow[0] * 128 + ldSeg * 16),
        (uint32_t)SWZ(ldRow[1] * 128 + ldSeg * 16),
        (uint32_t)SWZ(ldRow[2] * 128 + ldSeg * 16),
        (uint32_t)SWZ(ldRow[3] * 128 + ldSeg * 16)};

    float acc[2][8][4];
    #pragma unroll
    for (int mt = 0; mt < 2; mt++)
        #pragma unroll
        for (int nt = 0; nt < 8; nt++)
            #pragma unroll
            for (int q = 0; q < 4; q++) acc[mt][nt][q] = 0.f;

    const int blk = ln >> 3, r8 = ln & 7;

    // prefetch chunk 0
    {
        const uint32_t ab = aBase, bb = bBase;
        #pragma unroll
        for (int u = 0; u < 4; u++) {
            CPASYNC16(ab + ldOff[u], Arows + (size_t)ldRow[u] * C + ldSeg * 8);
            CPASYNC16(bb + ldOff[u], Brows + (size_t)ldRow[u] * C + ldSeg * 8);
        }
        CPCOMMIT();
    }

    #pragma unroll 1
    for (int ck = 0; ck < 8; ck++) {
        if (ck < 7) {
            const uint32_t ab = aBase + ((ck + 1) & 1) * 16384;
            const uint32_t bb = bBase + ((ck + 1) & 1) * 16384;
            const int co = (ck + 1) * 64;
            #pragma unroll
            for (int u = 0; u < 4; u++) {
                CPASYNC16(ab + ldOff[u], Arows + (size_t)ldRow[u] * C + co + ldSeg * 8);
                CPASYNC16(bb + ldOff[u], Brows + (size_t)ldRow[u] * C + co + ldSeg * 8);
            }
            CPCOMMIT();
            CPWAIT(1);
        } else {
            CPWAIT(0);
        }
        __syncthreads();

        const uint32_t ab = aBase + (ck & 1) * 16384;
        const uint32_t bb = bBase + (ck & 1) * 16384;
        #pragma unroll
        for (int ks = 0; ks < 4; ks++) {
            uint32_t af[2][4];
            #pragma unroll
            for (int mt = 0; mt < 2; mt++) {
                int row = wr * 32 + mt * 16 + (blk & 1) * 8 + r8;
                int unit = ks * 2 + (blk >> 1);
                LDSM4(af[mt][0], af[mt][1], af[mt][2], af[mt][3],
                      ab + SWZ(row * 128 + unit * 16));
            }
            uint32_t bf[4][4];
            #pragma unroll
            for (int nn = 0; nn < 4; nn++) {
                int row = wc * 64 + nn * 16 + (blk >> 1) * 8 + r8;
                int unit = ks * 2 + (blk & 1);
                LDSM4(bf[nn][0], bf[nn][1], bf[nn][2], bf[nn][3],
                      bb + SWZ(row * 128 + unit * 16));
            }
            #pragma unroll
            for (int mt = 0; mt < 2; mt++)
                #pragma unroll
                for (int nn = 0; nn < 4; nn++) {
                    MMA16816(acc[mt][2 * nn], af[mt], bf[nn][0], bf[nn][1]);
                    MMA16816(acc[mt][2 * nn + 1], af[mt], bf[nn][2], bf[nn][3]);
                }
        }
        __syncthreads();
    }

    // diagonal exclusion (only diag tile)
    if (i == j) {
        #pragma unroll
        for (int mt = 0; mt < 2; mt++)
            #pragma unroll
            for (int nt = 0; nt < 8; nt++)
                #pragma unroll
                for (int h = 0; h < 2; h++)
                    #pragma unroll
                    for (int q = 0; q < 2; q++) {
                        int rI = wr * 32 + mt * 16 + h * 8 + qr;
                        int cI = wc * 64 + nt * 8 + qc * 2 + q;
                        if (rI == cI) acc[mt][nt][h * 2 + q] = -INFINITY;
                    }
    }

    // ---- row-side LSE partials (slot j) ----
    #pragma unroll
    for (int mt = 0; mt < 2; mt++)
        #pragma unroll
        for (int h = 0; h < 2; h++) {
            float m = -INFINITY;
            #pragma unroll
            for (int nt = 0; nt < 8; nt++)
                m = fmaxf(m, fmaxf(acc[mt][nt][h * 2], acc[mt][nt][h * 2 + 1]));
            m = fmaxf(m, __shfl_xor_sync(0xffffffffu, m, 1));
            m = fmaxf(m, __shfl_xor_sync(0xffffffffu, m, 2));
            if (qc == 0) rmW[wc * 128 + wr * 32 + mt * 16 + h * 8 + qr] = m;
        }
    __syncthreads();
    #pragma unroll
    for (int mt = 0; mt < 2; mt++)
        #pragma unroll
        for (int h = 0; h < 2; h++) {
            int r = wr * 32 + mt * 16 + h * 8 + qr;
            float Mf = fmaxf(rmW[r], rmW[128 + r]);
            float thr = Mf - 17.0f;
            float s = 0.f;
            #pragma unroll
            for (int nt = 0; nt < 8; nt++)
                #pragma unroll
                for (int q = 0; q < 2; q++) {
                    float v = acc[mt][nt][h * 2 + q];
                    if (v > thr) s += __expf(v - Mf);
                }
            s += __shfl_xor_sync(0xffffffffu, s, 1);
            s += __shfl_xor_sync(0xffffffffu, s, 2);
            if (qc == 0) smW[wc * 128 + r] = s;
        }
    __syncthreads();
    if (tid < 128) {
        float Mf = fmaxf(rmW[tid], rmW[128 + tid]);
        float S = smW[tid] + smW[128 + tid];
        int gi = (b * NTILE + j) * L2 + i * 128 + tid;
        g_Mpart[gi] = Mf;
        g_Spart[gi] = S;
    }

    // ---- col-side LSE partials (slot i), only off-diagonal ----
    if (i != j) {
        #pragma unroll
        for (int nt = 0; nt < 8; nt++)
            #pragma unroll
            for (int q = 0; q < 2; q++) {
                float m = -INFINITY;
                #pragma unroll
                for (int mt = 0; mt < 2; mt++)
                    #pragma unroll
                    for (int h = 0; h < 2; h++)
                        m = fmaxf(m, acc[mt][nt][h * 2 + q]);
                m = fmaxf(m, __shfl_xor_sync(0xffffffffu, m, 4));
                m = fmaxf(m, __shfl_xor_sync(0xffffffffu, m, 8));
                m = fmaxf(m, __shfl_xor_sync(0xffffffffu, m, 16));
                if (qr == 0) cmW[wr * 128 + wc * 64 + nt * 8 + qc * 2 + q] = m;
            }
        __syncthreads();
        #pragma unroll
        for (int nt = 0; nt < 8; nt++)
            #pragma unroll
            for (int q = 0; q < 2; q++) {
                int cI = wc * 64 + nt * 8 + qc * 2 + q;
                float Mf = fmaxf(fmaxf(cmW[cI], cmW[128 + cI]),
                                 fmaxf(cmW[256 + cI], cmW[384 + cI]));
                float thr = Mf - 17.0f;
                float s = 0.f;
                #pragma unroll
                for (int mt = 0; mt < 2; mt++)
                    #pragma unroll
                    for (int h = 0; h < 2; h++) {
                        float v = acc[mt][nt][h * 2 + q];
                        if (v > thr) s += __expf(v - Mf);
                    }
                s += __shfl_xor_sync(0xffffffffu, s, 4);
                s += __shfl_xor_sync(0xffffffffu, s, 8);
                s += __shfl_xor_sync(0xffffffffu, s, 16);
                if (qr == 0) csW[wr * 128 + cI] = s;
            }
        __syncthreads();
        if (tid < 128) {
            float Mf = fmaxf(fmaxf(cmW[tid], cmW[128 + tid]),
                             fmaxf(cmW[256 + tid], cmW[384 + tid]));
            float S = csW[tid] + csW[128 + tid] + csW[256 + tid] + csW[384 + tid];
            int gi = (b * NTILE + i) * L2 + j * 128 + tid;
            g_Mpart[gi] = Mf;
            g_Spart[gi] = S;
        }
    }
}

// ----------------------------------------------------------------------------
// Kernel 3: combine 32 partials per row for one batch -> corrPart[b][t]
// ----------------------------------------------------------------------------
__global__ void combine_kernel() {
    int t = blockIdx.x * blockDim.x + threadIdx.x;
    int b = blockIdx.y;
    if (t >= L) return;
    float lse[2];
    #pragma unroll
    for (int hh = 0; hh < 2; hh++) {
        const int row = t + hh * L;
        float M = -INFINITY;
        #pragma unroll
        for (int ct = 0; ct < NTILE; ct++)
            M = fmaxf(M, g_Mpart[(b * NTILE + ct) * L2 + row]);
        float S = 0.f;
        #pragma unroll
        for (int ct = 0; ct < NTILE; ct++)
            S += g_Spart[(b * NTILE + ct) * L2 + row] *
                 __expf(g_Mpart[(b * NTILE + ct) * L2 + row] - M);
        lse[hh] = M + logf(S);
    }
    const float tAvg = 0.5f * (lse[0] + lse[1]);
    g_corrPart[b * L + t] =
        0.5f * g_instAvg[b * L + t] + 0.5f * tAvg - g_d[b * L + t];
}

// ----------------------------------------------------------------------------
// Kernel 4: top-32 candidate extraction (single warp, register-resident).
// ----------------------------------------------------------------------------
__global__ __launch_bounds__(32) void cand_kernel() {
    const int ln = threadIdx.x;
    float v[64];
    #pragma unroll
    for (int u = 0; u < 64; u++) {
        int idx = u * 32 + ln;
        v[u] = g_corrPart[idx] + g_corrPart[L + idx] +
               g_corrPart[2 * L + idx] + g_corrPart[3 * L + idx];
    }
    float pv = INFINITY;
    int pi = -1;
    for (int r = 0; r < NCAND; r++) {
        float bv = -INFINITY;
        int bi = 1 << 30;
        #pragma unroll
        for (int u = 0; u < 64; u++) {
            int idx = u * 32 + ln;
            bool lt = (v[u] < pv) || (v[u] == pv && idx > pi);
            if (lt && (v[u] > bv || (v[u] == bv && idx < bi))) { bv = v[u]; bi = idx; }
        }
        #pragma unroll
        for (int o = 16; o > 0; o >>= 1) {
            float ov = __shfl_xor_sync(0xffffffffu, bv, o);
            int oi = __shfl_xor_sync(0xffffffffu, bi, o);
            if (ov > bv || (ov == bv && oi < bi)) { bv = ov; bi = oi; }
        }
        if (ln == 0) g_cand[r] = bi;
        pv = bv; pi = bi;
    }
}

// ----------------------------------------------------------------------------
// Kernel 5: exact fp32 rescreen of candidates. Grid (32 col-blocks, B).
// ----------------------------------------------------------------------------
__global__ __launch_bounds__(256) void rescreen(const float* __restrict__ Q,
                                                const float* __restrict__ K) {
    const int blk = blockIdx.x, b = blockIdx.y;
    __shared__ float czT[32][64];
    __shared__ float colT[32][128];
    __shared__ float pr[16][64];
    __shared__ float Mrow[64];
    __shared__ int cand[NCAND];

    const int tid = threadIdx.x;
    const int tcg = tid >> 4, tcol = tid & 15;
    if (tid < NCAND) cand[tid] = g_cand[tid];
    __syncthreads();

    float sc[4][8];
    #pragma unroll
    for (int cc = 0; cc < 4; cc++)
        #pragma unroll
        for (int w = 0; w < 8; w++) sc[cc][w] = 0.f;

    for (int ck = 0; ck < 16; ck++) {
        __syncthreads();
        for (int idx = tid; idx < 64 * 32; idx += 256) {
            int r = idx >> 5, kk = idx & 31;
            int c = r >> 1, h = r & 1;
            int t = cand[c];
            const float* src = h ? (K + ((size_t)b * L + t) * C)
                                 : (Q + ((size_t)b * L + t) * C);
            czT[kk][r] = src[ck * 32 + kk];
        }
        for (int idx = tid; idx < 128 * 32; idx += 256) {
            int r = idx >> 5, kk = idx & 31;
            int gid = blk * 128 + r;
            const float* src = (gid < L) ? (Q + ((size_t)b * L + gid) * C)
                                         : (K + ((size_t)b * L + gid - L) * C);
            colT[kk][r] = src[ck * 32 + kk];
        }
        __syncthreads();
        #pragma unroll 4
        for (int kk = 0; kk < 32; kk++) {
            float a0 = czT[kk][tcg], a1 = czT[kk][tcg + 16];
            float a2 = czT[kk][tcg + 32], a3 = czT[kk][tcg + 48];
            float bv[8];
            #pragma unroll
            for (int w = 0; w < 8; w++) bv[w] = colT[kk][tcol + 16 * w];
            #pragma unroll
            for (int w = 0; w < 8; w++) {
                sc[0][w] = fmaf(a0, bv[w], sc[0][w]);
                sc[1][w] = fmaf(a1, bv[w], sc[1][w]);
                sc[2][w] = fmaf(a2, bv[w], sc[2][w]);
                sc[3][w] = fmaf(a3, bv[w], sc[3][w]);
            }
        }
    }

    #pragma unroll
    for (int cc = 0; cc < 4; cc++) {
        int ci = tcg + 16 * cc;
        int rowid = cand[ci >> 1] + (ci & 1) * L;
        #pragma unroll
        for (int w = 0; w < 8; w++) {
            int gid = blk * 128 + tcol + 16 * w;
            if (gid == rowid) sc[cc][w] = -INFINITY;
        }
    }

    __syncthreads();
    #pragma unroll
    for (int cc = 0; cc < 4; cc++) {
        int ci = tcg + 16 * cc;
        float m = sc[cc][0];
        #pragma unroll
        for (int w = 1; w < 8; w++) m = fmaxf(m, sc[cc][w]);
        pr[tcol][ci] = m;
    }
    __syncthreads();
    if (tid < 64) {
        float m = pr[0][tid];
        #pragma unroll
        for (int x = 1; x < 16; x++) m = fmaxf(m, pr[x][tid]);
        Mrow[tid] = m;
    }
    __syncthreads();
    #pragma unroll
    for (int cc = 0; cc < 4; cc++) {
        int ci = tcg + 16 * cc;
        float Mf = Mrow[ci];
        float s = 0.f;
        #pragma unroll
        for (int w = 0; w < 8; w++) s += __expf(sc[cc][w] - Mf);
        pr[tcol][ci] = s;
    }
    __syncthreads();
    if (tid < 64) {
        float s = 0.f;
        #pragma unroll
        for (int x = 0; x < 16; x++) s += pr[x][tid];
        int gi = (b * 64 + tid) * 32 + blk;
        g_cM[gi] = Mrow[tid];
        g_cS[gi] = s;
    }
}

// ----------------------------------------------------------------------------
// Kernel 6: final exact top-7 among candidates.
// ----------------------------------------------------------------------------
__global__ __launch_bounds__(64) void final_topk() {
    __shared__ float ls[B][64];
    __shared__ float val[NCAND];
    const int tid = threadIdx.x;
    if (tid < 64) {
        for (int b = 0; b < B; b++) {
            float M = -INFINITY;
            #pragma unroll
            for (int blk = 0; blk < 32; blk++)
                M = fmaxf(M, g_cM[(b * 64 + tid) * 32 + blk]);
            float S = 0.f;
            #pragma unroll
            for (int blk = 0; blk < 32; blk++)
                S += g_cS[(b * 64 + tid) * 32 + blk] *
                     __expf(g_cM[(b * 64 + tid) * 32 + blk] - M);
            ls[b][tid] = M + logf(S);
        }
    }
    __syncthreads();
    if (tid < NCAND) {
        int t = g_cand[tid];
        float sum = 0.f;
        for (int b = 0; b < B; b++) {
            float tavg = 0.5f * (ls[b][2 * tid] + ls[b][2 * tid + 1]);
            sum += 0.5f * g_instAvg[b * L + t] + 0.5f * tavg - g_d[b * L + t];
        }
        val[tid] = sum * 0.25f;
    }
    __syncthreads();
    if (tid == 0) {
        unsigned used = 0;
        for (int k = 0; k < TOPK; k++) {
            float best = -INFINITY;
            int bc = -1, bt = 1 << 30;
            for (int c = 0; c < NCAND; c++) {
                if ((used >> c) & 1) continue;
                int t = g_cand[c];
                if (val[c] > best || (val[c] == best && t < bt)) {
                    best = val[c]; bc = c; bt = t;
                }
            }
            used |= 1u << bc;
            g_topk[k] = g_cand[bc];
        }
    }
}

// ----------------------------------------------------------------------------
// Kernel 7a: chunk sums for cumsum. Grid (32 chunks, H, B), 64 threads.
// ----------------------------------------------------------------------------
__global__ __launch_bounds__(64) void cumsum_pass1(const float* __restrict__ V) {
    const int chunk = blockIdx.x, h = blockIdx.y, b = blockIdx.z;
    const int e = threadIdx.x;
    const long baseIn = (long)b * L * C + (long)h * E + e;
    const int l0 = chunk * 64;
    float s = 0.f;
    #pragma unroll 8
    for (int i = 0; i < 64; i++) s += V[baseIn + (long)(l0 + i) * C];
    g_csum[((b * H + h) * 32 + chunk) * E + e] = s;
}

// ----------------------------------------------------------------------------
// Kernel 7b: scan each chunk with offset; top-7 rows rescaled.
// Grid (32 chunks, H, B), 64 threads.
// ----------------------------------------------------------------------------
__global__ __launch_bounds__(64) void cumsum_pass2(const float* __restrict__ V,
                                                   float* __restrict__ out) {
    const int chunk = blockIdx.x, h = blockIdx.y, b = blockIdx.z;
    const int e = threadIdx.x;
    __shared__ int idx7[TOPK];
    if (threadIdx.x < TOPK) idx7[threadIdx.x] = g_topk[threadIdx.x];
    __syncthreads();

    float off = 0.f;
    for (int c = 0; c < chunk; c++)
        off += g_csum[((b * H + h) * 32 + c) * E + e];

    const long baseIn = (long)b * L * C + (long)h * E + e;
    const long baseOut = ((long)(b * H + h) * L) * E + e;
    const int l0 = chunk * 64;
    float acc = off;
    #pragma unroll 4
    for (int i = 0; i < 64; i++) {
        const int l = l0 + i;
        acc += V[baseIn + (long)l * C];
        float o = acc;
        #pragma unroll
        for (int k = 0; k < TOPK; k++)
            if (l == idx7[k]) o = acc / (float)(l + 1);
        out[baseOut + (long)l * E] = o;
    }
}

// ----------------------------------------------------------------------------
// Launch
// ----------------------------------------------------------------------------
extern "C" void kernel_launch(void* const* d_in, const int* in_sizes, int n_in,
                              void* d_out, int out_size) {
    const float* Q = (const float*)d_in[0];
    const float* K = (const float*)d_in[1];
    const float* V = (const float*)d_in[2];
    float* out = (float*)d_out;

    const int dynSmem = 65536;
    cudaFuncSetAttribute(temporal_mma, cudaFuncAttributeMaxDynamicSharedMemorySize,
                         dynSmem);

    convert_kernel<<<(B * L2 * C) / 8 / 256, 256>>>(Q, K);
    instance_kernel<<<L, 128>>>(Q, K);
    temporal_mma<<<dim3(NPAIR, B), 256, dynSmem>>>();
    combine_kernel<<<dim3(L / 256, B), 256>>>();
    cand_kernel<<<1, 32>>>();
    rescreen<<<dim3(32, B), 256>>>(Q, K);
    final_topk<<<1, 64>>>();
    cumsum_pass1<<<dim3(32, H, B), 64>>>(V);
    cumsum_pass2<<<dim3(32, H, B), 64>>>(V, out);
}

// round 6
// speedup vs baseline: 5.0957x; 1.1122x over previous
#include <cuda_runtime.h>
#include <cuda_bf16.h>
#include <math.h>
#include <stdint.h>

// ----------------------------------------------------------------------------
// Shapes (fixed)
// ----------------------------------------------------------------------------
#define B 4
#define L 2048
#define H 8
#define E 64
#define C 512
#define L2 4096
#define TOPK 7
#define NTILE 32
#define NPAIR 528
#define NCAND 16

// ----------------------------------------------------------------------------
// Device scratch
// ----------------------------------------------------------------------------
__device__ __nv_bfloat16 g_Zbf[(size_t)B * L2 * C];   // 16 MB bf16 Z = concat(q,k)
__device__ float g_Mpart[B * NTILE * L2];
__device__ float g_Spart[B * NTILE * L2];
__device__ float g_instAvg[B * L];
__device__ float g_d[B * L];
__device__ float g_corrPart[B * L];
__device__ int   g_cand[NCAND];
__device__ float g_cM[B * 2 * NCAND * 32];
__device__ float g_cS[B * 2 * NCAND * 32];
__device__ int   g_topk[TOPK];
__device__ float g_csum[B * H * 32 * E];

// ----------------------------------------------------------------------------
// Helpers
// ----------------------------------------------------------------------------
#define SWZ(o) ((o) ^ (((o) >> 3) & 0x70))

__device__ __forceinline__ uint32_t smem_u32(const void* p) {
    uint32_t a;
    asm("{ .reg .u64 t; cvta.to.shared.u64 t, %1; cvt.u32.u64 %0, t; }"
        : "=r"(a) : "l"(p));
    return a;
}

#define LDSM4(r0, r1, r2, r3, addr)                                             \
    asm volatile("ldmatrix.sync.aligned.m8n8.x4.shared.b16 {%0,%1,%2,%3}, [%4];" \
                 : "=r"(r0), "=r"(r1), "=r"(r2), "=r"(r3) : "r"(addr))

#define MMA16816(c, a, b0v, b1v)                                                \
    asm volatile("mma.sync.aligned.m16n8k16.row.col.f32.bf16.bf16.f32 "         \
                 "{%0,%1,%2,%3},{%4,%5,%6,%7},{%8,%9},{%0,%1,%2,%3};"           \
                 : "+f"((c)[0]), "+f"((c)[1]), "+f"((c)[2]), "+f"((c)[3])       \
                 : "r"((a)[0]), "r"((a)[1]), "r"((a)[2]), "r"((a)[3]),          \
                   "r"(b0v), "r"(b1v))

#define CPASYNC16(dst, src)                                                     \
    asm volatile("cp.async.cg.shared.global [%0], [%1], 16;"                    \
                 :: "r"(dst), "l"(src) : "memory")
#define CPCOMMIT() asm volatile("cp.async.commit_group;" ::: "memory")
#define CPWAIT(n)  asm volatile("cp.async.wait_group %0;" :: "n"(n) : "memory")

// ----------------------------------------------------------------------------
// Kernel 1: fused instance-CL + bf16 conversion. Per time t: loads the 8
// vectors {q[0..3,t], k[0..3,t]} once, computes the 8x8 instance gram + LSE,
// and writes the same rows into g_Zbf (bf16). grid = 1024 per launch (2 halves).
// ----------------------------------------------------------------------------
__global__ __launch_bounds__(128) void instance_conv(const float* __restrict__ Q,
                                                     const float* __restrict__ K,
                                                     int t0) {
    int t = t0 + blockIdx.x;
    __shared__ float z[8][C];
    __shared__ float G[8][8];
    __shared__ float lse[8];
    int tid = threadIdx.x;
    for (int idx = tid; idx < 8 * C; idx += 128) {
        int v = idx >> 9, c = idx & (C - 1);
        const float* src = (v < 4) ? (Q + ((long)v * L + t) * C)
                                   : (K + ((long)(v - 4) * L + t) * C);
        z[v][c] = src[c];
    }
    __syncthreads();

    // write bf16 rows to g_Zbf: batch b = v&3, row = t (q) or L+t (k)
    for (int idx = tid; idx < 8 * 128; idx += 128) {
        int v = idx >> 7, c4 = (idx & 127) * 4;
        int b = v & 3;
        long row = (v < 4) ? (long)t : (long)(L + t);
        __nv_bfloat162 h0 = __float22bfloat162_rn(make_float2(z[v][c4], z[v][c4 + 1]));
        __nv_bfloat162 h1 = __float22bfloat162_rn(make_float2(z[v][c4 + 2], z[v][c4 + 3]));
        uint2 o;
        o.x = *(uint32_t*)&h0; o.y = *(uint32_t*)&h1;
        *(uint2*)(g_Zbf + ((size_t)b * L2 + row) * C + c4) = o;
    }

    if (tid < 64) {
        int i = tid >> 3, j = tid & 7;
        float s = 0.f;
        #pragma unroll 8
        for (int c = 0; c < C; c++) s += z[i][c] * z[j][c];
        G[i][j] = s;
    }
    __syncthreads();
    if (tid < 8) {
        float m = -INFINITY;
        #pragma unroll
        for (int j = 0; j < 8; j++) if (j != tid) m = fmaxf(m, G[tid][j]);
        float s = 0.f;
        #pragma unroll
        for (int j = 0; j < 8; j++) if (j != tid) s += expf(G[tid][j] - m);
        lse[tid] = m + logf(s);
    }
    __syncthreads();
    if (tid < 4) {
        g_instAvg[tid * L + t] = 0.5f * (lse[tid] + lse[tid + 4]);
        g_d[tid * L + t] = G[tid][tid + 4];
    }
}

// ----------------------------------------------------------------------------
// Kernel 2: symmetric temporal gram via mma.sync bf16 + cp.async pipeline.
// Inner loop restructured for low register pressure (B-frags loaded per-nn)
// so __launch_bounds__(256,2) fits without local-memory spills.
// ----------------------------------------------------------------------------
__global__ __launch_bounds__(256, 2) void temporal_mma() {
    int p = blockIdx.x;
    int i = 0;
    while (p >= NTILE - i) { p -= NTILE - i; i++; }
    const int j = i + p;
    const int b = blockIdx.y;

    extern __shared__ __align__(1024) char dsm[];
    const uint32_t aBase = smem_u32(dsm);            // As[2]: 32 KB
    const uint32_t bBase = aBase + 32768;            // Bs[2]: 32 KB
    float* rmW = (float*)dsm;                        // reuse post-mainloop
    float* smW = rmW + 256;
    float* cmW = smW + 256;
    float* csW = cmW + 512;

    const int tid = threadIdx.x;
    const int ln = tid & 31;
    const int wr = (tid >> 5) >> 1, wc = (tid >> 5) & 1;
    const int qr = ln >> 2, qc = ln & 3;

    const __nv_bfloat16* Zb = g_Zbf + (size_t)b * L2 * C;
    const __nv_bfloat16* Arows = Zb + (size_t)i * 128 * C;
    const __nv_bfloat16* Brows = Zb + (size_t)j * 128 * C;

    const int ldSeg = tid & 7;

    float acc[2][8][4];
    #pragma unroll
    for (int mt = 0; mt < 2; mt++)
        #pragma unroll
        for (int nt = 0; nt < 8; nt++)
            #pragma unroll
            for (int q = 0; q < 4; q++) acc[mt][nt][q] = 0.f;

    const int blk = ln >> 3, r8 = ln & 7;

    // prefetch chunk 0
    {
        #pragma unroll
        for (int u = 0; u < 4; u++) {
            int row = (tid + u * 256) >> 3;
            uint32_t off = SWZ(row * 128 + ldSeg * 16);
            CPASYNC16(aBase + off, Arows + (size_t)row * C + ldSeg * 8);
            CPASYNC16(bBase + off, Brows + (size_t)row * C + ldSeg * 8);
        }
        CPCOMMIT();
    }

    #pragma unroll 1
    for (int ck = 0; ck < 8; ck++) {
        if (ck < 7) {
            const uint32_t abuf = aBase + ((ck + 1) & 1) * 16384;
            const uint32_t bbuf = bBase + ((ck + 1) & 1) * 16384;
            const int co = (ck + 1) * 64;
            #pragma unroll
            for (int u = 0; u < 4; u++) {
                int row = (tid + u * 256) >> 3;
                uint32_t off = SWZ(row * 128 + ldSeg * 16);
                CPASYNC16(abuf + off, Arows + (size_t)row * C + co + ldSeg * 8);
                CPASYNC16(bbuf + off, Brows + (size_t)row * C + co + ldSeg * 8);
            }
            CPCOMMIT();
            CPWAIT(1);
        } else {
            CPWAIT(0);
        }
        __syncthreads();

        const uint32_t ab = aBase + (ck & 1) * 16384;
        const uint32_t bb = bBase + (ck & 1) * 16384;
        #pragma unroll
        for (int ks = 0; ks < 4; ks++) {
            uint32_t af[2][4];
            #pragma unroll
            for (int mt = 0; mt < 2; mt++) {
                int row = wr * 32 + mt * 16 + (blk & 1) * 8 + r8;
                int unit = ks * 2 + (blk >> 1);
                LDSM4(af[mt][0], af[mt][1], af[mt][2], af[mt][3],
                      ab + SWZ(row * 128 + unit * 16));
            }
            #pragma unroll
            for (int nn = 0; nn < 4; nn++) {
                uint32_t bf0, bf1, bf2, bf3;
                int row = wc * 64 + nn * 16 + (blk >> 1) * 8 + r8;
                int unit = ks * 2 + (blk & 1);
                LDSM4(bf0, bf1, bf2, bf3, bb + SWZ(row * 128 + unit * 16));
                MMA16816(acc[0][2 * nn], af[0], bf0, bf1);
                MMA16816(acc[0][2 * nn + 1], af[0], bf2, bf3);
                MMA16816(acc[1][2 * nn], af[1], bf0, bf1);
                MMA16816(acc[1][2 * nn + 1], af[1], bf2, bf3);
            }
        }
        __syncthreads();
    }

    // diagonal exclusion (only diag tile)
    if (i == j) {
        #pragma unroll
        for (int mt = 0; mt < 2; mt++)
            #pragma unroll
            for (int nt = 0; nt < 8; nt++)
                #pragma unroll
                for (int h = 0; h < 2; h++)
                    #pragma unroll
                    for (int q = 0; q < 2; q++) {
                        int rI = wr * 32 + mt * 16 + h * 8 + qr;
                        int cI = wc * 64 + nt * 8 + qc * 2 + q;
                        if (rI == cI) acc[mt][nt][h * 2 + q] = -INFINITY;
                    }
    }

    // ---- row-side LSE partials (slot j) ----
    #pragma unroll
    for (int mt = 0; mt < 2; mt++)
        #pragma unroll
        for (int h = 0; h < 2; h++) {
            float m = -INFINITY;
            #pragma unroll
            for (int nt = 0; nt < 8; nt++)
                m = fmaxf(m, fmaxf(acc[mt][nt][h * 2], acc[mt][nt][h * 2 + 1]));
            m = fmaxf(m, __shfl_xor_sync(0xffffffffu, m, 1));
            m = fmaxf(m, __shfl_xor_sync(0xffffffffu, m, 2));
            if (qc == 0) rmW[wc * 128 + wr * 32 + mt * 16 + h * 8 + qr] = m;
        }
    __syncthreads();
    #pragma unroll
    for (int mt = 0; mt < 2; mt++)
        #pragma unroll
        for (int h = 0; h < 2; h++) {
            int r = wr * 32 + mt * 16 + h * 8 + qr;
            float Mf = fmaxf(rmW[r], rmW[128 + r]);
            float thr = Mf - 17.0f;
            float s = 0.f;
            #pragma unroll
            for (int nt = 0; nt < 8; nt++)
                #pragma unroll
                for (int q = 0; q < 2; q++) {
                    float v = acc[mt][nt][h * 2 + q];
                    if (v > thr) s += __expf(v - Mf);
                }
            s += __shfl_xor_sync(0xffffffffu, s, 1);
            s += __shfl_xor_sync(0xffffffffu, s, 2);
            if (qc == 0) smW[wc * 128 + r] = s;
        }
    __syncthreads();
    if (tid < 128) {
        float Mf = fmaxf(rmW[tid], rmW[128 + tid]);
        float S = smW[tid] + smW[128 + tid];
        int gi = (b * NTILE + j) * L2 + i * 128 + tid;
        g_Mpart[gi] = Mf;
        g_Spart[gi] = S;
    }

    // ---- col-side LSE partials (slot i), only off-diagonal ----
    if (i != j) {
        #pragma unroll
        for (int nt = 0; nt < 8; nt++)
            #pragma unroll
            for (int q = 0; q < 2; q++) {
                float m = -INFINITY;
                #pragma unroll
                for (int mt = 0; mt < 2; mt++)
                    #pragma unroll
                    for (int h = 0; h < 2; h++)
                        m = fmaxf(m, acc[mt][nt][h * 2 + q]);
                m = fmaxf(m, __shfl_xor_sync(0xffffffffu, m, 4));
                m = fmaxf(m, __shfl_xor_sync(0xffffffffu, m, 8));
                m = fmaxf(m, __shfl_xor_sync(0xffffffffu, m, 16));
                if (qr == 0) cmW[wr * 128 + wc * 64 + nt * 8 + qc * 2 + q] = m;
            }
        __syncthreads();
        #pragma unroll
        for (int nt = 0; nt < 8; nt++)
            #pragma unroll
            for (int q = 0; q < 2; q++) {
                int cI = wc * 64 + nt * 8 + qc * 2 + q;
                float Mf = fmaxf(fmaxf(cmW[cI], cmW[128 + cI]),
                                 fmaxf(cmW[256 + cI], cmW[384 + cI]));
                float thr = Mf - 17.0f;
                float s = 0.f;
                #pragma unroll
                for (int mt = 0; mt < 2; mt++)
                    #pragma unroll
                    for (int h = 0; h < 2; h++) {
                        float v = acc[mt][nt][h * 2 + q];
                        if (v > thr) s += __expf(v - Mf);
                    }
                s += __shfl_xor_sync(0xffffffffu, s, 4);
                s += __shfl_xor_sync(0xffffffffu, s, 8);
                s += __shfl_xor_sync(0xffffffffu, s, 16);
                if (qr == 0) csW[wr * 128 + cI] = s;
            }
        __syncthreads();
        if (tid < 128) {
            float Mf = fmaxf(fmaxf(cmW[tid], cmW[128 + tid]),
                             fmaxf(cmW[256 + tid], cmW[384 + tid]));
            float S = csW[tid] + csW[128 + tid] + csW[256 + tid] + csW[384 + tid];
            int gi = (b * NTILE + i) * L2 + j * 128 + tid;
            g_Mpart[gi] = Mf;
            g_Spart[gi] = S;
        }
    }
}

// ----------------------------------------------------------------------------
// Kernel 3: combine 32 partials per row for one batch -> corrPart[b][t]
// ----------------------------------------------------------------------------
__global__ void combine_kernel() {
    int t = blockIdx.x * blockDim.x + threadIdx.x;
    int b = blockIdx.y;
    if (t >= L) return;
    float lse[2];
    #pragma unroll
    for (int hh = 0; hh < 2; hh++) {
        const int row = t + hh * L;
        float M = -INFINITY;
        #pragma unroll
        for (int ct = 0; ct < NTILE; ct++)
            M = fmaxf(M, g_Mpart[(b * NTILE + ct) * L2 + row]);
        float S = 0.f;
        #pragma unroll
        for (int ct = 0; ct < NTILE; ct++)
            S += g_Spart[(b * NTILE + ct) * L2 + row] *
                 __expf(g_Mpart[(b * NTILE + ct) * L2 + row] - M);
        lse[hh] = M + logf(S);
    }
    const float tAvg = 0.5f * (lse[0] + lse[1]);
    g_corrPart[b * L + t] =
        0.5f * g_instAvg[b * L + t] + 0.5f * tAvg - g_d[b * L + t];
}

// ----------------------------------------------------------------------------
// Kernel 4: top-NCAND candidate extraction (single warp).
// ----------------------------------------------------------------------------
__global__ __launch_bounds__(32) void cand_kernel() {
    const int ln = threadIdx.x;
    float v[64];
    #pragma unroll
    for (int u = 0; u < 64; u++) {
        int idx = u * 32 + ln;
        v[u] = g_corrPart[idx] + g_corrPart[L + idx] +
               g_corrPart[2 * L + idx] + g_corrPart[3 * L + idx];
    }
    float pv = INFINITY;
    int pi = -1;
    for (int r = 0; r < NCAND; r++) {
        float bv = -INFINITY;
        int bi = 1 << 30;
        #pragma unroll
        for (int u = 0; u < 64; u++) {
            int idx = u * 32 + ln;
            bool lt = (v[u] < pv) || (v[u] == pv && idx > pi);
            if (lt && (v[u] > bv || (v[u] == bv && idx < bi))) { bv = v[u]; bi = idx; }
        }
        #pragma unroll
        for (int o = 16; o > 0; o >>= 1) {
            float ov = __shfl_xor_sync(0xffffffffu, bv, o);
            int oi = __shfl_xor_sync(0xffffffffu, bi, o);
            if (ov > bv || (ov == bv && oi < bi)) { bv = ov; bi = oi; }
        }
        if (ln == 0) g_cand[r] = bi;
        pv = bv; pi = bi;
    }
}

// ----------------------------------------------------------------------------
// Kernel 5: exact fp32 rescreen of NCAND candidates. Grid (32 col-blocks, B).
// 32 candidate rows ({q,k} per cand), thread rows tcg and tcg+16.
// ----------------------------------------------------------------------------
__global__ __launch_bounds__(256) void rescreen(const float* __restrict__ Q,
                                                const float* __restrict__ K) {
    const int blk = blockIdx.x, b = blockIdx.y;
    __shared__ float czT[32][32];
    __shared__ float colT[32][128];
    __shared__ float pr[16][32];
    __shared__ float Mrow[32];
    __shared__ int cand[NCAND];

    const int tid = threadIdx.x;
    const int tcg = tid >> 4, tcol = tid & 15;
    if (tid < NCAND) cand[tid] = g_cand[tid];
    __syncthreads();

    float sc[2][8];
    #pragma unroll
    for (int cc = 0; cc < 2; cc++)
        #pragma unroll
        for (int w = 0; w < 8; w++) sc[cc][w] = 0.f;

    for (int ck = 0; ck < 16; ck++) {
        __syncthreads();
        for (int idx = tid; idx < 32 * 32; idx += 256) {
            int r = idx >> 5, kk = idx & 31;
            int c = r >> 1, h = r & 1;
            int t = cand[c];
            const float* src = h ? (K + ((size_t)b * L + t) * C)
                                 : (Q + ((size_t)b * L + t) * C);
            czT[kk][r] = src[ck * 32 + kk];
        }
        for (int idx = tid; idx < 128 * 32; idx += 256) {
            int r = idx >> 5, kk = idx & 31;
            int gid = blk * 128 + r;
            const float* src = (gid < L) ? (Q + ((size_t)b * L + gid) * C)
                                         : (K + ((size_t)b * L + gid - L) * C);
            colT[kk][r] = src[ck * 32 + kk];
        }
        __syncthreads();
        #pragma unroll 4
        for (int kk = 0; kk < 32; kk++) {
            float a0 = czT[kk][tcg], a1 = czT[kk][tcg + 16];
            float bv[8];
            #pragma unroll
            for (int w = 0; w < 8; w++) bv[w] = colT[kk][tcol + 16 * w];
            #pragma unroll
            for (int w = 0; w < 8; w++) {
                sc[0][w] = fmaf(a0, bv[w], sc[0][w]);
                sc[1][w] = fmaf(a1, bv[w], sc[1][w]);
            }
        }
    }

    #pragma unroll
    for (int cc = 0; cc < 2; cc++) {
        int ci = tcg + 16 * cc;
        int rowid = cand[ci >> 1] + (ci & 1) * L;
        #pragma unroll
        for (int w = 0; w < 8; w++) {
            int gid = blk * 128 + tcol + 16 * w;
            if (gid == rowid) sc[cc][w] = -INFINITY;
        }
    }

    __syncthreads();
    #pragma unroll
    for (int cc = 0; cc < 2; cc++) {
        int ci = tcg + 16 * cc;
        float m = sc[cc][0];
        #pragma unroll
        for (int w = 1; w < 8; w++) m = fmaxf(m, sc[cc][w]);
        pr[tcol][ci] = m;
    }
    __syncthreads();
    if (tid < 32) {
        float m = pr[0][tid];
        #pragma unroll
        for (int x = 1; x < 16; x++) m = fmaxf(m, pr[x][tid]);
        Mrow[tid] = m;
    }
    __syncthreads();
    #pragma unroll
    for (int cc = 0; cc < 2; cc++) {
        int ci = tcg + 16 * cc;
        float Mf = Mrow[ci];
        float s = 0.f;
        #pragma unroll
        for (int w = 0; w < 8; w++) s += __expf(sc[cc][w] - Mf);
        pr[tcol][ci] = s;
    }
    __syncthreads();
    if (tid < 32) {
        float s = 0.f;
        #pragma unroll
        for (int x = 0; x < 16; x++) s += pr[x][tid];
        int gi = (b * 32 + tid) * 32 + blk;
        g_cM[gi] = Mrow[tid];
        g_cS[gi] = s;
    }
}

// ----------------------------------------------------------------------------
// Kernel 6: final exact top-7 among candidates.
// ----------------------------------------------------------------------------
__global__ __launch_bounds__(32) void final_topk() {
    __shared__ float ls[B][32];
    __shared__ float val[NCAND];
    const int tid = threadIdx.x;
    for (int b = 0; b < B; b++) {
        float M = -INFINITY;
        #pragma unroll
        for (int blk = 0; blk < 32; blk++)
            M = fmaxf(M, g_cM[(b * 32 + tid) * 32 + blk]);
        float S = 0.f;
        #pragma unroll
        for (int blk = 0; blk < 32; blk++)
            S += g_cS[(b * 32 + tid) * 32 + blk] *
                 __expf(g_cM[(b * 32 + tid) * 32 + blk] - M);
        ls[b][tid] = M + logf(S);
    }
    __syncwarp();
    if (tid < NCAND) {
        int t = g_cand[tid];
        float sum = 0.f;
        for (int b = 0; b < B; b++) {
            float tavg = 0.5f * (ls[b][2 * tid] + ls[b][2 * tid + 1]);
            sum += 0.5f * g_instAvg[b * L + t] + 0.5f * tavg - g_d[b * L + t];
        }
        val[tid] = sum * 0.25f;
    }
    __syncwarp();
    if (tid == 0) {
        unsigned used = 0;
        for (int k = 0; k < TOPK; k++) {
            float best = -INFINITY;
            int bc = -1, bt = 1 << 30;
            for (int c = 0; c < NCAND; c++) {
                if ((used >> c) & 1) continue;
                int t = g_cand[c];
                if (val[c] > best || (val[c] == best && t < bt)) {
                    best = val[c]; bc = c; bt = t;
                }
            }
            used |= 1u << bc;
            g_topk[k] = g_cand[bc];
        }
    }
}

// ----------------------------------------------------------------------------
// Kernel 7a: chunk sums for cumsum. Grid (32 chunks, H, B), 64 threads.
// ----------------------------------------------------------------------------
__global__ __launch_bounds__(64) void cumsum_pass1(const float* __restrict__ V) {
    const int chunk = blockIdx.x, h = blockIdx.y, b = blockIdx.z;
    const int e = threadIdx.x;
    const long baseIn = (long)b * L * C + (long)h * E + e;
    const int l0 = chunk * 64;
    float s = 0.f;
    #pragma unroll 8
    for (int i = 0; i < 64; i++) s += V[baseIn + (long)(l0 + i) * C];
    g_csum[((b * H + h) * 32 + chunk) * E + e] = s;
}

// ----------------------------------------------------------------------------
// Kernel 7b: scan each chunk with offset; top-7 rows rescaled.
// ----------------------------------------------------------------------------
__global__ __launch_bounds__(64) void cumsum_pass2(const float* __restrict__ V,
                                                   float* __restrict__ out) {
    const int chunk = blockIdx.x, h = blockIdx.y, b = blockIdx.z;
    const int e = threadIdx.x;
    __shared__ int idx7[TOPK];
    if (threadIdx.x < TOPK) idx7[threadIdx.x] = g_topk[threadIdx.x];
    __syncthreads();

    float off = 0.f;
    for (int c = 0; c < chunk; c++)
        off += g_csum[((b * H + h) * 32 + c) * E + e];

    const long baseIn = (long)b * L * C + (long)h * E + e;
    const long baseOut = ((long)(b * H + h) * L) * E + e;
    const int l0 = chunk * 64;
    float acc = off;
    #pragma unroll 4
    for (int i = 0; i < 64; i++) {
        const int l = l0 + i;
        acc += V[baseIn + (long)l * C];
        float o = acc;
        #pragma unroll
        for (int k = 0; k < TOPK; k++)
            if (l == idx7[k]) o = acc / (float)(l + 1);
        out[baseOut + (long)l * E] = o;
    }
}

// ----------------------------------------------------------------------------
// Launch (temporal_mma is the 4th launch -> gets the ncu profile slot)
// ----------------------------------------------------------------------------
extern "C" void kernel_launch(void* const* d_in, const int* in_sizes, int n_in,
                              void* d_out, int out_size) {
    const float* Q = (const float*)d_in[0];
    const float* K = (const float*)d_in[1];
    const float* V = (const float*)d_in[2];
    float* out = (float*)d_out;

    const int dynSmem = 65536;
    cudaFuncSetAttribute(temporal_mma, cudaFuncAttributeMaxDynamicSharedMemorySize,
                         dynSmem);

    instance_conv<<<L / 2, 128>>>(Q, K, 0);
    instance_conv<<<L / 2, 128>>>(Q, K, L / 2);
    cumsum_pass1<<<dim3(32, H, B), 64>>>(V);
    temporal_mma<<<dim3(NPAIR, B), 256, dynSmem>>>();
    combine_kernel<<<dim3(L / 256, B), 256>>>();
    cand_kernel<<<1, 32>>>();
    rescreen<<<dim3(32, B), 256>>>(Q, K);
    final_topk<<<1, 32>>>();
    cumsum_pass2<<<dim3(32, H, B), 64>>>(V, out);
}

// round 7
// speedup vs baseline: 5.9340x; 1.1645x over previous
#include <cuda_runtime.h>
#include <cuda_bf16.h>
#include <math.h>
#include <stdint.h>

// ----------------------------------------------------------------------------
// Shapes (fixed)
// ----------------------------------------------------------------------------
#define B 4
#define L 2048
#define H 8
#define E 64
#define C 512
#define L2 4096
#define TOPK 7
#define NTILE 32
#define NPAIR 528
#define NCAND 16
#define NRSB 64            // rescreen col-blocks (64 cols each)

// ----------------------------------------------------------------------------
// Device scratch
// ----------------------------------------------------------------------------
__device__ __nv_bfloat16 g_Zbf[(size_t)B * L2 * C];   // 16 MB bf16 Z = concat(q,k)
__device__ float g_Mpart[B * NTILE * L2];
__device__ float g_Spart[B * NTILE * L2];
__device__ float g_instAvg[B * L];
__device__ float g_d[B * L];
__device__ float g_corrPart[B * L];
__device__ int   g_cand[NCAND];
__device__ float g_cM[B * 2 * NCAND * NRSB];
__device__ float g_cS[B * 2 * NCAND * NRSB];
__device__ int   g_topk[TOPK];
__device__ float g_csum[B * H * 32 * E];

// ----------------------------------------------------------------------------
// Helpers
// ----------------------------------------------------------------------------
#define SWZ(o) ((o) ^ (((o) >> 3) & 0x70))

__device__ __forceinline__ uint32_t smem_u32(const void* p) {
    uint32_t a;
    asm("{ .reg .u64 t; cvta.to.shared.u64 t, %1; cvt.u32.u64 %0, t; }"
        : "=r"(a) : "l"(p));
    return a;
}

#define LDSM4(r0, r1, r2, r3, addr)                                             \
    asm volatile("ldmatrix.sync.aligned.m8n8.x4.shared.b16 {%0,%1,%2,%3}, [%4];" \
                 : "=r"(r0), "=r"(r1), "=r"(r2), "=r"(r3) : "r"(addr))

#define MMA16816(c, a, b0v, b1v)                                                \
    asm volatile("mma.sync.aligned.m16n8k16.row.col.f32.bf16.bf16.f32 "         \
                 "{%0,%1,%2,%3},{%4,%5,%6,%7},{%8,%9},{%0,%1,%2,%3};"           \
                 : "+f"((c)[0]), "+f"((c)[1]), "+f"((c)[2]), "+f"((c)[3])       \
                 : "r"((a)[0]), "r"((a)[1]), "r"((a)[2]), "r"((a)[3]),          \
                   "r"(b0v), "r"(b1v))

#define CPASYNC16(dst, src)                                                     \
    asm volatile("cp.async.cg.shared.global [%0], [%1], 16;"                    \
                 :: "r"(dst), "l"(src) : "memory")
#define CPCOMMIT() asm volatile("cp.async.commit_group;" ::: "memory")
#define CPWAIT(n)  asm volatile("cp.async.wait_group %0;" :: "n"(n) : "memory")

// upper-triangle index for 8x8 symmetric gram: i<=j
#define TRI(i, j) ((i) * (15 - (i)) / 2 + (j))

// ----------------------------------------------------------------------------
// Kernel 0: convert Q,K fp32 -> bf16 Z (rows: q then k, per batch)
// ----------------------------------------------------------------------------
__global__ __launch_bounds__(256) void convert_kernel(const float* __restrict__ Q,
                                                      const float* __restrict__ K) {
    long t = (long)blockIdx.x * 256 + threadIdx.x;
    long e = t * 8;
    int b = (int)(e / ((long)L2 * C));
    long r = e % ((long)L2 * C);
    int row = (int)(r / C);
    int k = (int)(r % C);
    const float* src = (row < L) ? Q + ((long)b * L + row) * C + k
                                 : K + ((long)b * L + (row - L)) * C + k;
    float4 f0 = *(const float4*)(src);
    float4 f1 = *(const float4*)(src + 4);
    __nv_bfloat162 h0 = __float22bfloat162_rn(make_float2(f0.x, f0.y));
    __nv_bfloat162 h1 = __float22bfloat162_rn(make_float2(f0.z, f0.w));
    __nv_bfloat162 h2 = __float22bfloat162_rn(make_float2(f1.x, f1.y));
    __nv_bfloat162 h3 = __float22bfloat162_rn(make_float2(f1.z, f1.w));
    uint4 o;
    o.x = *(uint32_t*)&h0; o.y = *(uint32_t*)&h1;
    o.z = *(uint32_t*)&h2; o.w = *(uint32_t*)&h3;
    *(uint4*)(g_Zbf + e) = o;
}

// ----------------------------------------------------------------------------
// Kernel 1: instance-CL, warp-per-t, register accumulators.
// 36 upper-tri pair dots over C=512 (lane owns col c = ck*32+lane), xor-shuffle
// all-reduce, then every lane computes all 8 LSEs (uniform), lanes 0..3 write.
// ----------------------------------------------------------------------------
__global__ __launch_bounds__(128) void instance_kernel(const float* __restrict__ Q,
                                                       const float* __restrict__ K) {
    const int wid = threadIdx.x >> 5, ln = threadIdx.x & 31;
    const int t = blockIdx.x * 4 + wid;

    float acc[36];
    #pragma unroll
    for (int p = 0; p < 36; p++) acc[p] = 0.f;

    #pragma unroll 2
    for (int ck = 0; ck < 16; ck++) {
        const int c = ck * 32 + ln;
        float z[8];
        #pragma unroll
        for (int v = 0; v < 4; v++) z[v] = __ldg(Q + ((size_t)v * L + t) * C + c);
        #pragma unroll
        for (int v = 0; v < 4; v++) z[4 + v] = __ldg(K + ((size_t)v * L + t) * C + c);
        int p = 0;
        #pragma unroll
        for (int i = 0; i < 8; i++)
            #pragma unroll
            for (int j = i; j < 8; j++) { acc[p] = fmaf(z[i], z[j], acc[p]); p++; }
    }

    #pragma unroll
    for (int p = 0; p < 36; p++) {
        #pragma unroll
        for (int o = 16; o > 0; o >>= 1)
            acc[p] += __shfl_xor_sync(0xffffffffu, acc[p], o);
    }

    // uniform LSE per row (all lanes redundantly)
    float lse[8];
    #pragma unroll
    for (int r = 0; r < 8; r++) {
        float m = -INFINITY;
        #pragma unroll
        for (int j = 0; j < 8; j++) {
            if (j == r) continue;
            float g = (j < r) ? acc[TRI(j, r)] : acc[TRI(r, j)];
            m = fmaxf(m, g);
        }
        float s = 0.f;
        #pragma unroll
        for (int j = 0; j < 8; j++) {
            if (j == r) continue;
            float g = (j < r) ? acc[TRI(j, r)] : acc[TRI(r, j)];
            s += __expf(g - m);
        }
        lse[r] = m + logf(s);
    }

    if (ln < 4) {
        g_instAvg[ln * L + t] = 0.5f * (lse[ln] + lse[ln + 4]);
        g_d[ln * L + t] = acc[TRI(ln, ln + 4)];
    }
}

// ----------------------------------------------------------------------------
// Kernel 2: symmetric temporal gram via mma.sync bf16 + cp.async pipeline.
// Inner-loop addresses swizzle-free: for fixed row, SWZ(row*128+unit*16) =
// rowbase + ((ks ^ p) << 5) with p = ((row*16)>>5)&3 (XOR permutes ks field).
// ----------------------------------------------------------------------------
__global__ __launch_bounds__(256, 2) void temporal_mma() {
    int p = blockIdx.x;
    int i = 0;
    while (p >= NTILE - i) { p -= NTILE - i; i++; }
    const int j = i + p;
    const int b = blockIdx.y;

    extern __shared__ __align__(1024) char dsm[];
    const uint32_t aBase = smem_u32(dsm);            // As[2]: 32 KB
    const uint32_t bBase = aBase + 32768;            // Bs[2]: 32 KB
    float* rmW = (float*)dsm;                        // reuse post-mainloop
    float* smW = rmW + 256;
    float* cmW = smW + 256;
    float* csW = cmW + 512;

    const int tid = threadIdx.x;
    const int ln = tid & 31;
    const int wr = (tid >> 5) >> 1, wc = (tid >> 5) & 1;
    const int qr = ln >> 2, qc = ln & 3;

    const __nv_bfloat16* Zb = g_Zbf + (size_t)b * L2 * C;
    const __nv_bfloat16* Arows = Zb + (size_t)i * 128 * C;
    const __nv_bfloat16* Brows = Zb + (size_t)j * 128 * C;

    // cp.async per-thread slots (precomputed once)
    const int ldSeg = tid & 7;
    const int ldRow[4] = {(tid + 0) >> 3, (tid + 256) >> 3,
                          (tid + 512) >> 3, (tid + 768) >> 3};
    const uint32_t ldOff[4] = {
        (uint32_t)SWZ(ldRow[0] * 128 + ldSeg * 16),
        (uint32_t)SWZ(ldRow[1] * 128 + ldSeg * 16),
        (uint32_t)SWZ(ldRow[2] * 128 + ldSeg * 16),
        (uint32_t)SWZ(ldRow[3] * 128 + ldSeg * 16)};

    const int blk = ln >> 3, r8 = ln & 7;

    // swizzle-free LDSM address bases
    const int rowA0 = wr * 32 + (blk & 1) * 8 + r8;          // mt adds +16
    const int maskA = (rowA0 * 16) & 0x70;
    const uint32_t pA = (uint32_t)(maskA >> 5);              // 2 bits
    const uint32_t cA0 = rowA0 * 128 + ((((blk >> 1) << 4)) ^ (maskA & 0x10));
    const uint32_t cA1 = cA0 + 16 * 128;

    const int rowB0 = wc * 64 + (blk >> 1) * 8 + r8;         // nn adds +16
    const int maskB = (rowB0 * 16) & 0x70;
    const uint32_t pB = (uint32_t)(maskB >> 5);
    const uint32_t cB0 = rowB0 * 128 + ((((blk & 1) << 4)) ^ (maskB & 0x10));

    float acc[2][8][4];
    #pragma unroll
    for (int mt = 0; mt < 2; mt++)
        #pragma unroll
        for (int nt = 0; nt < 8; nt++)
            #pragma unroll
            for (int q = 0; q < 4; q++) acc[mt][nt][q] = 0.f;

    // prefetch chunk 0
    {
        #pragma unroll
        for (int u = 0; u < 4; u++) {
            CPASYNC16(aBase + ldOff[u], Arows + (size_t)ldRow[u] * C + ldSeg * 8);
            CPASYNC16(bBase + ldOff[u], Brows + (size_t)ldRow[u] * C + ldSeg * 8);
        }
        CPCOMMIT();
    }

    #pragma unroll 1
    for (int ck = 0; ck < 8; ck++) {
        if (ck < 7) {
            const uint32_t abuf = aBase + ((ck + 1) & 1) * 16384;
            const uint32_t bbuf = bBase + ((ck + 1) & 1) * 16384;
            const int co = (ck + 1) * 64;
            #pragma unroll
            for (int u = 0; u < 4; u++) {
                CPASYNC16(abuf + ldOff[u], Arows + (size_t)ldRow[u] * C + co + ldSeg * 8);
                CPASYNC16(bbuf + ldOff[u], Brows + (size_t)ldRow[u] * C + co + ldSeg * 8);
            }
            CPCOMMIT();
            CPWAIT(1);
        } else {
            CPWAIT(0);
        }
        __syncthreads();

        const uint32_t abA = aBase + (ck & 1) * 16384;
        const uint32_t bbB = bBase + (ck & 1) * 16384;
        #pragma unroll
        for (uint32_t ks = 0; ks < 4; ks++) {
            const uint32_t offA = ((ks ^ pA) << 5);
            const uint32_t offB = ((ks ^ pB) << 5);
            uint32_t af[2][4];
            LDSM4(af[0][0], af[0][1], af[0][2], af[0][3], abA + cA0 + offA);
            LDSM4(af[1][0], af[1][1], af[1][2], af[1][3], abA + cA1 + offA);
            #pragma unroll
            for (int nn = 0; nn < 4; nn++) {
                uint32_t bf0, bf1, bf2, bf3;
                LDSM4(bf0, bf1, bf2, bf3, bbB + cB0 + nn * (16 * 128) + offB);
                MMA16816(acc[0][2 * nn], af[0], bf0, bf1);
                MMA16816(acc[0][2 * nn + 1], af[0], bf2, bf3);
                MMA16816(acc[1][2 * nn], af[1], bf0, bf1);
                MMA16816(acc[1][2 * nn + 1], af[1], bf2, bf3);
            }
        }
        __syncthreads();
    }

    // diagonal exclusion (only diag tile)
    if (i == j) {
        #pragma unroll
        for (int mt = 0; mt < 2; mt++)
            #pragma unroll
            for (int nt = 0; nt < 8; nt++)
                #pragma unroll
                for (int h = 0; h < 2; h++)
                    #pragma unroll
                    for (int q = 0; q < 2; q++) {
                        int rI = wr * 32 + mt * 16 + h * 8 + qr;
                        int cI = wc * 64 + nt * 8 + qc * 2 + q;
                        if (rI == cI) acc[mt][nt][h * 2 + q] = -INFINITY;
                    }
    }

    // ---- row-side LSE partials (slot j) ----
    #pragma unroll
    for (int mt = 0; mt < 2; mt++)
        #pragma unroll
        for (int h = 0; h < 2; h++) {
            float m = -INFINITY;
            #pragma unroll
            for (int nt = 0; nt < 8; nt++)
                m = fmaxf(m, fmaxf(acc[mt][nt][h * 2], acc[mt][nt][h * 2 + 1]));
            m = fmaxf(m, __shfl_xor_sync(0xffffffffu, m, 1));
            m = fmaxf(m, __shfl_xor_sync(0xffffffffu, m, 2));
            if (qc == 0) rmW[wc * 128 + wr * 32 + mt * 16 + h * 8 + qr] = m;
        }
    __syncthreads();
    #pragma unroll
    for (int mt = 0; mt < 2; mt++)
        #pragma unroll
        for (int h = 0; h < 2; h++) {
            int r = wr * 32 + mt * 16 + h * 8 + qr;
            float Mf = fmaxf(rmW[r], rmW[128 + r]);
            float thr = Mf - 17.0f;
            float s = 0.f;
            #pragma unroll
            for (int nt = 0; nt < 8; nt++)
                #pragma unroll
                for (int q = 0; q < 2; q++) {
                    float v = acc[mt][nt][h * 2 + q];
                    if (v > thr) s += __expf(v - Mf);
                }
            s += __shfl_xor_sync(0xffffffffu, s, 1);
            s += __shfl_xor_sync(0xffffffffu, s, 2);
            if (qc == 0) smW[wc * 128 + r] = s;
        }
    __syncthreads();
    if (tid < 128) {
        float Mf = fmaxf(rmW[tid], rmW[128 + tid]);
        float S = smW[tid] + smW[128 + tid];
        int gi = (b * NTILE + j) * L2 + i * 128 + tid;
        g_Mpart[gi] = Mf;
        g_Spart[gi] = S;
    }

    // ---- col-side LSE partials (slot i), only off-diagonal ----
    if (i != j) {
        #pragma unroll
        for (int nt = 0; nt < 8; nt++)
            #pragma unroll
            for (int q = 0; q < 2; q++) {
                float m = -INFINITY;
                #pragma unroll
                for (int mt = 0; mt < 2; mt++)
                    #pragma unroll
                    for (int h = 0; h < 2; h++)
                        m = fmaxf(m, acc[mt][nt][h * 2 + q]);
                m = fmaxf(m, __shfl_xor_sync(0xffffffffu, m, 4));
                m = fmaxf(m, __shfl_xor_sync(0xffffffffu, m, 8));
                m = fmaxf(m, __shfl_xor_sync(0xffffffffu, m, 16));
                if (qr == 0) cmW[wr * 128 + wc * 64 + nt * 8 + qc * 2 + q] = m;
            }
        __syncthreads();
        #pragma unroll
        for (int nt = 0; nt < 8; nt++)
            #pragma unroll
            for (int q = 0; q < 2; q++) {
                int cI = wc * 64 + nt * 8 + qc * 2 + q;
                float Mf = fmaxf(fmaxf(cmW[cI], cmW[128 + cI]),
                                 fmaxf(cmW[256 + cI], cmW[384 + cI]));
                float thr = Mf - 17.0f;
                float s = 0.f;
                #pragma unroll
                for (int mt = 0; mt < 2; mt++)
                    #pragma unroll
                    for (int h = 0; h < 2; h++) {
                        float v = acc[mt][nt][h * 2 + q];
                        if (v > thr) s += __expf(v - Mf);
                    }
                s += __shfl_xor_sync(0xffffffffu, s, 4);
                s += __shfl_xor_sync(0xffffffffu, s, 8);
                s += __shfl_xor_sync(0xffffffffu, s, 16);
                if (qr == 0) csW[wr * 128 + cI] = s;
            }
        __syncthreads();
        if (tid < 128) {
            float Mf = fmaxf(fmaxf(cmW[tid], cmW[128 + tid]),
                             fmaxf(cmW[256 + tid], cmW[384 + tid]));
            float S = csW[tid] + csW[128 + tid] + csW[256 + tid] + csW[384 + tid];
            int gi = (b * NTILE + i) * L2 + j * 128 + tid;
            g_Mpart[gi] = Mf;
            g_Spart[gi] = S;
        }
    }
}

// ----------------------------------------------------------------------------
// Kernel 3: combine 32 partials per row for one batch -> corrPart[b][t]
// ----------------------------------------------------------------------------
__global__ void combine_kernel() {
    int t = blockIdx.x * blockDim.x + threadIdx.x;
    int b = blockIdx.y;
    if (t >= L) return;
    float lse[2];
    #pragma unroll
    for (int hh = 0; hh < 2; hh++) {
        const int row = t + hh * L;
        float M = -INFINITY;
        #pragma unroll
        for (int ct = 0; ct < NTILE; ct++)
            M = fmaxf(M, g_Mpart[(b * NTILE + ct) * L2 + row]);
        float S = 0.f;
        #pragma unroll
        for (int ct = 0; ct < NTILE; ct++)
            S += g_Spart[(b * NTILE + ct) * L2 + row] *
                 __expf(g_Mpart[(b * NTILE + ct) * L2 + row] - M);
        lse[hh] = M + logf(S);
    }
    const float tAvg = 0.5f * (lse[0] + lse[1]);
    g_corrPart[b * L + t] =
        0.5f * g_instAvg[b * L + t] + 0.5f * tAvg - g_d[b * L + t];
}

// ----------------------------------------------------------------------------
// Kernel 4: top-NCAND candidate extraction (single warp).
// ----------------------------------------------------------------------------
__global__ __launch_bounds__(32) void cand_kernel() {
    const int ln = threadIdx.x;
    float v[64];
    #pragma unroll
    for (int u = 0; u < 64; u++) {
        int idx = u * 32 + ln;
        v[u] = g_corrPart[idx] + g_corrPart[L + idx] +
               g_corrPart[2 * L + idx] + g_corrPart[3 * L + idx];
    }
    float pv = INFINITY;
    int pi = -1;
    for (int r = 0; r < NCAND; r++) {
        float bv = -INFINITY;
        int bi = 1 << 30;
        #pragma unroll
        for (int u = 0; u < 64; u++) {
            int idx = u * 32 + ln;
            bool lt = (v[u] < pv) || (v[u] == pv && idx > pi);
            if (lt && (v[u] > bv || (v[u] == bv && idx < bi))) { bv = v[u]; bi = idx; }
        }
        #pragma unroll
        for (int o = 16; o > 0; o >>= 1) {
            float ov = __shfl_xor_sync(0xffffffffu, bv, o);
            int oi = __shfl_xor_sync(0xffffffffu, bi, o);
            if (ov > bv || (ov == bv && oi < bi)) { bv = ov; bi = oi; }
        }
        if (ln == 0) g_cand[r] = bi;
        pv = bv; pi = bi;
    }
}

// ----------------------------------------------------------------------------
// Kernel 5: exact fp32 rescreen of NCAND candidates. Grid (NRSB=64, B),
// 64 gram-columns per block. Thread rows tcg, tcg+16; cols tcol+16w (w<4).
// ----------------------------------------------------------------------------
__global__ __launch_bounds__(256) void rescreen(const float* __restrict__ Q,
                                                const float* __restrict__ K) {
    const int blk = blockIdx.x, b = blockIdx.y;
    __shared__ float czT[32][32];
    __shared__ float colT[32][64];
    __shared__ float pr[16][32];
    __shared__ float Mrow[32];
    __shared__ int cand[NCAND];

    const int tid = threadIdx.x;
    const int tcg = tid >> 4, tcol = tid & 15;
    if (tid < NCAND) cand[tid] = g_cand[tid];
    __syncthreads();

    float sc[2][4];
    #pragma unroll
    for (int cc = 0; cc < 2; cc++)
        #pragma unroll
        for (int w = 0; w < 4; w++) sc[cc][w] = 0.f;

    for (int ck = 0; ck < 16; ck++) {
        __syncthreads();
        for (int idx = tid; idx < 32 * 32; idx += 256) {
            int r = idx >> 5, kk = idx & 31;
            int c = r >> 1, h = r & 1;
            int t = cand[c];
            const float* src = h ? (K + ((size_t)b * L + t) * C)
                                 : (Q + ((size_t)b * L + t) * C);
            czT[kk][r] = src[ck * 32 + kk];
        }
        for (int idx = tid; idx < 64 * 32; idx += 256) {
            int r = idx >> 5, kk = idx & 31;
            int gid = blk * 64 + r;
            const float* src = (gid < L) ? (Q + ((size_t)b * L + gid) * C)
                                         : (K + ((size_t)b * L + gid - L) * C);
            colT[kk][r] = src[ck * 32 + kk];
        }
        __syncthreads();
        #pragma unroll 4
        for (int kk = 0; kk < 32; kk++) {
            float a0 = czT[kk][tcg], a1 = czT[kk][tcg + 16];
            float bv[4];
            #pragma unroll
            for (int w = 0; w < 4; w++) bv[w] = colT[kk][tcol + 16 * w];
            #pragma unroll
            for (int w = 0; w < 4; w++) {
                sc[0][w] = fmaf(a0, bv[w], sc[0][w]);
                sc[1][w] = fmaf(a1, bv[w], sc[1][w]);
            }
        }
    }

    #pragma unroll
    for (int cc = 0; cc < 2; cc++) {
        int ci = tcg + 16 * cc;
        int rowid = cand[ci >> 1] + (ci & 1) * L;
        #pragma unroll
        for (int w = 0; w < 4; w++) {
            int gid = blk * 64 + tcol + 16 * w;
            if (gid == rowid) sc[cc][w] = -INFINITY;
        }
    }

    __syncthreads();
    #pragma unroll
    for (int cc = 0; cc < 2; cc++) {
        int ci = tcg + 16 * cc;
        float m = sc[cc][0];
        #pragma unroll
        for (int w = 1; w < 4; w++) m = fmaxf(m, sc[cc][w]);
        pr[tcol][ci] = m;
    }
    __syncthreads();
    if (tid < 32) {
        float m = pr[0][tid];
        #pragma unroll
        for (int x = 1; x < 16; x++) m = fmaxf(m, pr[x][tid]);
        Mrow[tid] = m;
    }
    __syncthreads();
    #pragma unroll
    for (int cc = 0; cc < 2; cc++) {
        int ci = tcg + 16 * cc;
        float Mf = Mrow[ci];
        float s = 0.f;
        #pragma unroll
        for (int w = 0; w < 4; w++) s += __expf(sc[cc][w] - Mf);
        pr[tcol][ci] = s;
    }
    __syncthreads();
    if (tid < 32) {
        float s = 0.f;
        #pragma unroll
        for (int x = 0; x < 16; x++) s += pr[x][tid];
        int gi = (b * 32 + tid) * NRSB + blk;
        g_cM[gi] = Mrow[tid];
        g_cS[gi] = s;
    }
}

// ----------------------------------------------------------------------------
// Kernel 6: final exact top-7 among candidates.
// ----------------------------------------------------------------------------
__global__ __launch_bounds__(32) void final_topk() {
    __shared__ float ls[B][32];
    __shared__ float val[NCAND];
    const int tid = threadIdx.x;
    for (int b = 0; b < B; b++) {
        float M = -INFINITY;
        #pragma unroll
        for (int blk = 0; blk < NRSB; blk++)
            M = fmaxf(M, g_cM[(b * 32 + tid) * NRSB + blk]);
        float S = 0.f;
        #pragma unroll
        for (int blk = 0; blk < NRSB; blk++)
            S += g_cS[(b * 32 + tid) * NRSB + blk] *
                 __expf(g_cM[(b * 32 + tid) * NRSB + blk] - M);
        ls[b][tid] = M + logf(S);
    }
    __syncwarp();
    if (tid < NCAND) {
        int t = g_cand[tid];
        float sum = 0.f;
        for (int b = 0; b < B; b++) {
            float tavg = 0.5f * (ls[b][2 * tid] + ls[b][2 * tid + 1]);
            sum += 0.5f * g_instAvg[b * L + t] + 0.5f * tavg - g_d[b * L + t];
        }
        val[tid] = sum * 0.25f;
    }
    __syncwarp();
    if (tid == 0) {
        unsigned used = 0;
        for (int k = 0; k < TOPK; k++) {
            float best = -INFINITY;
            int bc = -1, bt = 1 << 30;
            for (int c = 0; c < NCAND; c++) {
                if ((used >> c) & 1) continue;
                int t = g_cand[c];
                if (val[c] > best || (val[c] == best && t < bt)) {
                    best = val[c]; bc = c; bt = t;
                }
            }
            used |= 1u << bc;
            g_topk[k] = g_cand[bc];
        }
    }
}

// ----------------------------------------------------------------------------
// Kernel 7a: chunk sums for cumsum. Grid (32 chunks, H, B), 64 threads.
// ----------------------------------------------------------------------------
__global__ __launch_bounds__(64) void cumsum_pass1(const float* __restrict__ V) {
    const int chunk = blockIdx.x, h = blockIdx.y, b = blockIdx.z;
    const int e = threadIdx.x;
    const long baseIn = (long)b * L * C + (long)h * E + e;
    const int l0 = chunk * 64;
    float s = 0.f;
    #pragma unroll 8
    for (int i = 0; i < 64; i++) s += V[baseIn + (long)(l0 + i) * C];
    g_csum[((b * H + h) * 32 + chunk) * E + e] = s;
}

// ----------------------------------------------------------------------------
// Kernel 7b: scan each chunk with offset; top-7 rows rescaled.
// ----------------------------------------------------------------------------
__global__ __launch_bounds__(64) void cumsum_pass2(const float* __restrict__ V,
                                                   float* __restrict__ out) {
    const int chunk = blockIdx.x, h = blockIdx.y, b = blockIdx.z;
    const int e = threadIdx.x;
    __shared__ int idx7[TOPK];
    if (threadIdx.x < TOPK) idx7[threadIdx.x] = g_topk[threadIdx.x];
    __syncthreads();

    float off = 0.f;
    for (int c = 0; c < chunk; c++)
        off += g_csum[((b * H + h) * 32 + c) * E + e];

    const long baseIn = (long)b * L * C + (long)h * E + e;
    const long baseOut = ((long)(b * H + h) * L) * E + e;
    const int l0 = chunk * 64;
    float acc = off;
    #pragma unroll 4
    for (int i = 0; i < 64; i++) {
        const int l = l0 + i;
        acc += V[baseIn + (long)l * C];
        float o = acc;
        #pragma unroll
        for (int k = 0; k < TOPK; k++)
            if (l == idx7[k]) o = acc / (float)(l + 1);
        out[baseOut + (long)l * E] = o;
    }
}

// ----------------------------------------------------------------------------
// Launch (temporal_mma kept as the 4th launch -> ncu profile slot)
// ----------------------------------------------------------------------------
extern "C" void kernel_launch(void* const* d_in, const int* in_sizes, int n_in,
                              void* d_out, int out_size) {
    const float* Q = (const float*)d_in[0];
    const float* K = (const float*)d_in[1];
    const float* V = (const float*)d_in[2];
    float* out = (float*)d_out;

    const int dynSmem = 65536;
    cudaFuncSetAttribute(temporal_mma, cudaFuncAttributeMaxDynamicSharedMemorySize,
                         dynSmem);

    convert_kernel<<<(B * L2 * C) / 8 / 256, 256>>>(Q, K);
    instance_kernel<<<L / 4, 128>>>(Q, K);
    cumsum_pass1<<<dim3(32, H, B), 64>>>(V);
    temporal_mma<<<dim3(NPAIR, B), 256, dynSmem>>>();
    combine_kernel<<<dim3(L / 256, B), 256>>>();
    cand_kernel<<<1, 32>>>();
    rescreen<<<dim3(NRSB, B), 256>>>(Q, K);
    final_topk<<<1, 32>>>();
    cumsum_pass2<<<dim3(32, H, B), 64>>>(V, out);
}

// round 8
// speedup vs baseline: 6.1683x; 1.0395x over previous
#include <cuda_runtime.h>
#include <cuda_bf16.h>
#include <math.h>
#include <stdint.h>

// ----------------------------------------------------------------------------
// Shapes (fixed)
// ----------------------------------------------------------------------------
#define B 4
#define L 2048
#define H 8
#define E 64
#define C 512
#define L2 4096
#define TOPK 7
#define NTILE 32
#define NPAIR 528
#define NCAND 16
#define NRSB 64            // rescreen col-blocks (64 cols each)

// ----------------------------------------------------------------------------
// Device scratch
// ----------------------------------------------------------------------------
__device__ __nv_bfloat16 g_Zbf[(size_t)B * L2 * C];   // 16 MB bf16 Z = concat(q,k)
__device__ float g_Mpart[B * NTILE * L2];
__device__ float g_Spart[B * NTILE * L2];
__device__ float g_instAvg[B * L];
__device__ float g_d[B * L];
__device__ float g_corrPart[B * L];
__device__ int   g_cand[NCAND];
__device__ float g_cM[B * 2 * NCAND * NRSB];
__device__ float g_cS[B * 2 * NCAND * NRSB];
__device__ int   g_topk[TOPK];
__device__ float g_csum[B * H * 32 * E];

// ----------------------------------------------------------------------------
// Helpers
// ----------------------------------------------------------------------------
#define SWZ(o) ((o) ^ (((o) >> 3) & 0x70))

__device__ __forceinline__ uint32_t smem_u32(const void* p) {
    uint32_t a;
    asm("{ .reg .u64 t; cvta.to.shared.u64 t, %1; cvt.u32.u64 %0, t; }"
        : "=r"(a) : "l"(p));
    return a;
}

#define LDSM4(r0, r1, r2, r3, addr)                                             \
    asm volatile("ldmatrix.sync.aligned.m8n8.x4.shared.b16 {%0,%1,%2,%3}, [%4];" \
                 : "=r"(r0), "=r"(r1), "=r"(r2), "=r"(r3) : "r"(addr))

#define MMA16816(c, a, b0v, b1v)                                                \
    asm volatile("mma.sync.aligned.m16n8k16.row.col.f32.bf16.bf16.f32 "         \
                 "{%0,%1,%2,%3},{%4,%5,%6,%7},{%8,%9},{%0,%1,%2,%3};"           \
                 : "+f"((c)[0]), "+f"((c)[1]), "+f"((c)[2]), "+f"((c)[3])       \
                 : "r"((a)[0]), "r"((a)[1]), "r"((a)[2]), "r"((a)[3]),          \
                   "r"(b0v), "r"(b1v))

#define CPASYNC16(dst, src)                                                     \
    asm volatile("cp.async.cg.shared.global [%0], [%1], 16;"                    \
                 :: "r"(dst), "l"(src) : "memory")
#define CPCOMMIT() asm volatile("cp.async.commit_group;" ::: "memory")
#define CPWAIT(n)  asm volatile("cp.async.wait_group %0;" :: "n"(n) : "memory")

// upper-triangle index for 8x8 symmetric gram: i<=j
#define TRI(i, j) ((i) * (15 - (i)) / 2 + (j))

// ----------------------------------------------------------------------------
// Kernel 0: convert Q,K fp32 -> bf16 Z (rows: q then k, per batch)
// ----------------------------------------------------------------------------
__global__ __launch_bounds__(256) void convert_kernel(const float* __restrict__ Q,
                                                      const float* __restrict__ K) {
    long t = (long)blockIdx.x * 256 + threadIdx.x;
    long e = t * 8;
    int b = (int)(e / ((long)L2 * C));
    long r = e % ((long)L2 * C);
    int row = (int)(r / C);
    int k = (int)(r % C);
    const float* src = (row < L) ? Q + ((long)b * L + row) * C + k
                                 : K + ((long)b * L + (row - L)) * C + k;
    float4 f0 = *(const float4*)(src);
    float4 f1 = *(const float4*)(src + 4);
    __nv_bfloat162 h0 = __float22bfloat162_rn(make_float2(f0.x, f0.y));
    __nv_bfloat162 h1 = __float22bfloat162_rn(make_float2(f0.z, f0.w));
    __nv_bfloat162 h2 = __float22bfloat162_rn(make_float2(f1.x, f1.y));
    __nv_bfloat162 h3 = __float22bfloat162_rn(make_float2(f1.z, f1.w));
    uint4 o;
    o.x = *(uint32_t*)&h0; o.y = *(uint32_t*)&h1;
    o.z = *(uint32_t*)&h2; o.w = *(uint32_t*)&h3;
    *(uint4*)(g_Zbf + e) = o;
}

// ----------------------------------------------------------------------------
// Kernel 1: instance-CL, warp-per-t, register accumulators.
// ----------------------------------------------------------------------------
__global__ __launch_bounds__(128) void instance_kernel(const float* __restrict__ Q,
                                                       const float* __restrict__ K) {
    const int wid = threadIdx.x >> 5, ln = threadIdx.x & 31;
    const int t = blockIdx.x * 4 + wid;

    float acc[36];
    #pragma unroll
    for (int p = 0; p < 36; p++) acc[p] = 0.f;

    #pragma unroll 2
    for (int ck = 0; ck < 16; ck++) {
        const int c = ck * 32 + ln;
        float z[8];
        #pragma unroll
        for (int v = 0; v < 4; v++) z[v] = __ldg(Q + ((size_t)v * L + t) * C + c);
        #pragma unroll
        for (int v = 0; v < 4; v++) z[4 + v] = __ldg(K + ((size_t)v * L + t) * C + c);
        int p = 0;
        #pragma unroll
        for (int i = 0; i < 8; i++)
            #pragma unroll
            for (int j = i; j < 8; j++) { acc[p] = fmaf(z[i], z[j], acc[p]); p++; }
    }

    #pragma unroll
    for (int p = 0; p < 36; p++) {
        #pragma unroll
        for (int o = 16; o > 0; o >>= 1)
            acc[p] += __shfl_xor_sync(0xffffffffu, acc[p], o);
    }

    float lse[8];
    #pragma unroll
    for (int r = 0; r < 8; r++) {
        float m = -INFINITY;
        #pragma unroll
        for (int j = 0; j < 8; j++) {
            if (j == r) continue;
            float g = (j < r) ? acc[TRI(j, r)] : acc[TRI(r, j)];
            m = fmaxf(m, g);
        }
        float s = 0.f;
        #pragma unroll
        for (int j = 0; j < 8; j++) {
            if (j == r) continue;
            float g = (j < r) ? acc[TRI(j, r)] : acc[TRI(r, j)];
            s += __expf(g - m);
        }
        lse[r] = m + logf(s);
    }

    if (ln < 4) {
        g_instAvg[ln * L + t] = 0.5f * (lse[ln] + lse[ln + 4]);
        g_d[ln * L + t] = acc[TRI(ln, ln + 4)];
    }
}

// ----------------------------------------------------------------------------
// Kernel 2: symmetric temporal gram, mma.sync bf16, 64x64 warp tile.
// 128 threads = 4 warps in 2x2 (wr row-half, wc col-half) -> 128x128 CTA tile.
// Per ks: 4 A-LDSM + 4 B-LDSM feed 32 MMA16816 (MMA-bound, not LDSM-bound).
// Swizzle-free inner addressing (mask invariant under row+16).
// ----------------------------------------------------------------------------
__global__ __launch_bounds__(128, 2) void temporal_mma() {
    int p = blockIdx.x;
    int i = 0;
    while (p >= NTILE - i) { p -= NTILE - i; i++; }
    const int j = i + p;
    const int b = blockIdx.y;

    extern __shared__ __align__(1024) char dsm[];
    const uint32_t aBase = smem_u32(dsm);            // As[2]: 32 KB
    const uint32_t bBase = aBase + 32768;            // Bs[2]: 32 KB
    float* rmW = (float*)dsm;                        // reuse post-mainloop
    float* smW = rmW + 256;
    float* cmW = smW + 256;
    float* csW = cmW + 256;

    const int tid = threadIdx.x;
    const int ln = tid & 31;
    const int wr = (tid >> 5) >> 1, wc = (tid >> 5) & 1;
    const int qr = ln >> 2, qc = ln & 3;

    const __nv_bfloat16* Zb = g_Zbf + (size_t)b * L2 * C;
    const __nv_bfloat16* Arows = Zb + (size_t)i * 128 * C;
    const __nv_bfloat16* Brows = Zb + (size_t)j * 128 * C;

    // cp.async per-thread slots: 8 units per array per chunk (128 threads)
    const int ldSeg = tid & 7;
    int ldRow[8];
    uint32_t ldOff[8];
    #pragma unroll
    for (int u = 0; u < 8; u++) {
        ldRow[u] = (tid + u * 128) >> 3;
        ldOff[u] = (uint32_t)SWZ(ldRow[u] * 128 + ldSeg * 16);
    }

    const int blk = ln >> 3, r8 = ln & 7;

    // swizzle-free LDSM bases (mask invariant as row += 16)
    const int rowA0 = wr * 64 + (blk & 1) * 8 + r8;          // mt adds +16
    const int maskA = (rowA0 * 16) & 0x70;
    const uint32_t pA = (uint32_t)(maskA >> 5);
    const uint32_t cA0 = rowA0 * 128 + ((((blk >> 1) << 4)) ^ (maskA & 0x10));

    const int rowB0 = wc * 64 + (blk >> 1) * 8 + r8;         // nn adds +16
    const int maskB = (rowB0 * 16) & 0x70;
    const uint32_t pB = (uint32_t)(maskB >> 5);
    const uint32_t cB0 = rowB0 * 128 + ((((blk & 1) << 4)) ^ (maskB & 0x10));

    float acc[4][8][4];
    #pragma unroll
    for (int mt = 0; mt < 4; mt++)
        #pragma unroll
        for (int nt = 0; nt < 8; nt++)
            #pragma unroll
            for (int q = 0; q < 4; q++) acc[mt][nt][q] = 0.f;

    // prefetch chunk 0
    {
        #pragma unroll
        for (int u = 0; u < 8; u++) {
            CPASYNC16(aBase + ldOff[u], Arows + (size_t)ldRow[u] * C + ldSeg * 8);
            CPASYNC16(bBase + ldOff[u], Brows + (size_t)ldRow[u] * C + ldSeg * 8);
        }
        CPCOMMIT();
    }

    #pragma unroll 1
    for (int ck = 0; ck < 8; ck++) {
        if (ck < 7) {
            const uint32_t abuf = aBase + ((ck + 1) & 1) * 16384;
            const uint32_t bbuf = bBase + ((ck + 1) & 1) * 16384;
            const int co = (ck + 1) * 64;
            #pragma unroll
            for (int u = 0; u < 8; u++) {
                CPASYNC16(abuf + ldOff[u], Arows + (size_t)ldRow[u] * C + co + ldSeg * 8);
                CPASYNC16(bbuf + ldOff[u], Brows + (size_t)ldRow[u] * C + co + ldSeg * 8);
            }
            CPCOMMIT();
            CPWAIT(1);
        } else {
            CPWAIT(0);
        }
        __syncthreads();

        const uint32_t abA = aBase + (ck & 1) * 16384;
        const uint32_t bbB = bBase + (ck & 1) * 16384;
        #pragma unroll
        for (uint32_t ks = 0; ks < 4; ks++) {
            const uint32_t offA = ((ks ^ pA) << 5);
            const uint32_t offB = ((ks ^ pB) << 5);
            uint32_t af[4][4];
            #pragma unroll
            for (int mt = 0; mt < 4; mt++)
                LDSM4(af[mt][0], af[mt][1], af[mt][2], af[mt][3],
                      abA + cA0 + mt * (16 * 128) + offA);
            #pragma unroll
            for (int nn = 0; nn < 4; nn++) {
                uint32_t bf0, bf1, bf2, bf3;
                LDSM4(bf0, bf1, bf2, bf3, bbB + cB0 + nn * (16 * 128) + offB);
                #pragma unroll
                for (int mt = 0; mt < 4; mt++) {
                    MMA16816(acc[mt][2 * nn], af[mt], bf0, bf1);
                    MMA16816(acc[mt][2 * nn + 1], af[mt], bf2, bf3);
                }
            }
        }
        __syncthreads();
    }

    // diagonal exclusion (only diag tile)
    if (i == j) {
        #pragma unroll
        for (int mt = 0; mt < 4; mt++)
            #pragma unroll
            for (int nt = 0; nt < 8; nt++)
                #pragma unroll
                for (int h = 0; h < 2; h++)
                    #pragma unroll
                    for (int q = 0; q < 2; q++) {
                        int rI = wr * 64 + mt * 16 + h * 8 + qr;
                        int cI = wc * 64 + nt * 8 + qc * 2 + q;
                        if (rI == cI) acc[mt][nt][h * 2 + q] = -INFINITY;
                    }
    }

    // ---- row-side LSE partials (slot j) ----
    #pragma unroll
    for (int mt = 0; mt < 4; mt++)
        #pragma unroll
        for (int h = 0; h < 2; h++) {
            float m = -INFINITY;
            #pragma unroll
            for (int nt = 0; nt < 8; nt++)
                m = fmaxf(m, fmaxf(acc[mt][nt][h * 2], acc[mt][nt][h * 2 + 1]));
            m = fmaxf(m, __shfl_xor_sync(0xffffffffu, m, 1));
            m = fmaxf(m, __shfl_xor_sync(0xffffffffu, m, 2));
            if (qc == 0) rmW[wc * 128 + wr * 64 + mt * 16 + h * 8 + qr] = m;
        }
    __syncthreads();
    #pragma unroll
    for (int mt = 0; mt < 4; mt++)
        #pragma unroll
        for (int h = 0; h < 2; h++) {
            int r = wr * 64 + mt * 16 + h * 8 + qr;
            float Mf = fmaxf(rmW[r], rmW[128 + r]);
            float thr = Mf - 17.0f;
            float s = 0.f;
            #pragma unroll
            for (int nt = 0; nt < 8; nt++)
                #pragma unroll
                for (int q = 0; q < 2; q++) {
                    float v = acc[mt][nt][h * 2 + q];
                    if (v > thr) s += __expf(v - Mf);
                }
            s += __shfl_xor_sync(0xffffffffu, s, 1);
            s += __shfl_xor_sync(0xffffffffu, s, 2);
            if (qc == 0) smW[wc * 128 + r] = s;
        }
    __syncthreads();
    if (tid < 128) {
        float Mf = fmaxf(rmW[tid], rmW[128 + tid]);
        float S = smW[tid] + smW[128 + tid];
        int gi = (b * NTILE + j) * L2 + i * 128 + tid;
        g_Mpart[gi] = Mf;
        g_Spart[gi] = S;
    }

    // ---- col-side LSE partials (slot i), only off-diagonal ----
    if (i != j) {
        #pragma unroll
        for (int nt = 0; nt < 8; nt++)
            #pragma unroll
            for (int q = 0; q < 2; q++) {
                float m = -INFINITY;
                #pragma unroll
                for (int mt = 0; mt < 4; mt++)
                    #pragma unroll
                    for (int h = 0; h < 2; h++)
                        m = fmaxf(m, acc[mt][nt][h * 2 + q]);
                m = fmaxf(m, __shfl_xor_sync(0xffffffffu, m, 4));
                m = fmaxf(m, __shfl_xor_sync(0xffffffffu, m, 8));
                m = fmaxf(m, __shfl_xor_sync(0xffffffffu, m, 16));
                if (qr == 0) cmW[wr * 128 + wc * 64 + nt * 8 + qc * 2 + q] = m;
            }
        __syncthreads();
        #pragma unroll
        for (int nt = 0; nt < 8; nt++)
            #pragma unroll
            for (int q = 0; q < 2; q++) {
                int cI = wc * 64 + nt * 8 + qc * 2 + q;
                float Mf = fmaxf(cmW[cI], cmW[128 + cI]);
                float thr = Mf - 17.0f;
                float s = 0.f;
                #pragma unroll
                for (int mt = 0; mt < 4; mt++)
                    #pragma unroll
                    for (int h = 0; h < 2; h++) {
                        float v = acc[mt][nt][h * 2 + q];
                        if (v > thr) s += __expf(v - Mf);
                    }
                s += __shfl_xor_sync(0xffffffffu, s, 4);
                s += __shfl_xor_sync(0xffffffffu, s, 8);
                s += __shfl_xor_sync(0xffffffffu, s, 16);
                if (qr == 0) csW[wr * 128 + cI] = s;
            }
        __syncthreads();
        if (tid < 128) {
            float Mf = fmaxf(cmW[tid], cmW[128 + tid]);
            float S = csW[tid] + csW[128 + tid];
            int gi = (b * NTILE + i) * L2 + j * 128 + tid;
            g_Mpart[gi] = Mf;
            g_Spart[gi] = S;
        }
    }
}

// ----------------------------------------------------------------------------
// Kernel 3: combine 32 partials per row for one batch -> corrPart[b][t]
// ----------------------------------------------------------------------------
__global__ void combine_kernel() {
    int t = blockIdx.x * blockDim.x + threadIdx.x;
    int b = blockIdx.y;
    if (t >= L) return;
    float lse[2];
    #pragma unroll
    for (int hh = 0; hh < 2; hh++) {
        const int row = t + hh * L;
        float M = -INFINITY;
        #pragma unroll
        for (int ct = 0; ct < NTILE; ct++)
            M = fmaxf(M, g_Mpart[(b * NTILE + ct) * L2 + row]);
        float S = 0.f;
        #pragma unroll
        for (int ct = 0; ct < NTILE; ct++)
            S += g_Spart[(b * NTILE + ct) * L2 + row] *
                 __expf(g_Mpart[(b * NTILE + ct) * L2 + row] - M);
        lse[hh] = M + logf(S);
    }
    const float tAvg = 0.5f * (lse[0] + lse[1]);
    g_corrPart[b * L + t] =
        0.5f * g_instAvg[b * L + t] + 0.5f * tAvg - g_d[b * L + t];
}

// ----------------------------------------------------------------------------
// Kernel 4: top-NCAND candidate extraction (single warp).
// ----------------------------------------------------------------------------
__global__ __launch_bounds__(32) void cand_kernel() {
    const int ln = threadIdx.x;
    float v[64];
    #pragma unroll
    for (int u = 0; u < 64; u++) {
        int idx = u * 32 + ln;
        v[u] = g_corrPart[idx] + g_corrPart[L + idx] +
               g_corrPart[2 * L + idx] + g_corrPart[3 * L + idx];
    }
    float pv = INFINITY;
    int pi = -1;
    for (int r = 0; r < NCAND; r++) {
        float bv = -INFINITY;
        int bi = 1 << 30;
        #pragma unroll
        for (int u = 0; u < 64; u++) {
            int idx = u * 32 + ln;
            bool lt = (v[u] < pv) || (v[u] == pv && idx > pi);
            if (lt && (v[u] > bv || (v[u] == bv && idx < bi))) { bv = v[u]; bi = idx; }
        }
        #pragma unroll
        for (int o = 16; o > 0; o >>= 1) {
            float ov = __shfl_xor_sync(0xffffffffu, bv, o);
            int oi = __shfl_xor_sync(0xffffffffu, bi, o);
            if (ov > bv || (ov == bv && oi < bi)) { bv = ov; bi = oi; }
        }
        if (ln == 0) g_cand[r] = bi;
        pv = bv; pi = bi;
    }
}

// ----------------------------------------------------------------------------
// Kernel 5: exact fp32 rescreen of NCAND candidates. Grid (NRSB=64, B).
// ----------------------------------------------------------------------------
__global__ __launch_bounds__(256) void rescreen(const float* __restrict__ Q,
                                                const float* __restrict__ K) {
    const int blk = blockIdx.x, b = blockIdx.y;
    __shared__ float czT[32][32];
    __shared__ float colT[32][64];
    __shared__ float pr[16][32];
    __shared__ float Mrow[32];
    __shared__ int cand[NCAND];

    const int tid = threadIdx.x;
    const int tcg = tid >> 4, tcol = tid & 15;
    if (tid < NCAND) cand[tid] = g_cand[tid];
    __syncthreads();

    float sc[2][4];
    #pragma unroll
    for (int cc = 0; cc < 2; cc++)
        #pragma unroll
        for (int w = 0; w < 4; w++) sc[cc][w] = 0.f;

    for (int ck = 0; ck < 16; ck++) {
        __syncthreads();
        for (int idx = tid; idx < 32 * 32; idx += 256) {
            int r = idx >> 5, kk = idx & 31;
            int c = r >> 1, h = r & 1;
            int t = cand[c];
            const float* src = h ? (K + ((size_t)b * L + t) * C)
                                 : (Q + ((size_t)b * L + t) * C);
            czT[kk][r] = src[ck * 32 + kk];
        }
        for (int idx = tid; idx < 64 * 32; idx += 256) {
            int r = idx >> 5, kk = idx & 31;
            int gid = blk * 64 + r;
            const float* src = (gid < L) ? (Q + ((size_t)b * L + gid) * C)
                                         : (K + ((size_t)b * L + gid - L) * C);
            colT[kk][r] = src[ck * 32 + kk];
        }
        __syncthreads();
        #pragma unroll 4
        for (int kk = 0; kk < 32; kk++) {
            float a0 = czT[kk][tcg], a1 = czT[kk][tcg + 16];
            float bv[4];
            #pragma unroll
            for (int w = 0; w < 4; w++) bv[w] = colT[kk][tcol + 16 * w];
            #pragma unroll
            for (int w = 0; w < 4; w++) {
                sc[0][w] = fmaf(a0, bv[w], sc[0][w]);
                sc[1][w] = fmaf(a1, bv[w], sc[1][w]);
            }
        }
    }

    #pragma unroll
    for (int cc = 0; cc < 2; cc++) {
        int ci = tcg + 16 * cc;
        int rowid = cand[ci >> 1] + (ci & 1) * L;
        #pragma unroll
        for (int w = 0; w < 4; w++) {
            int gid = blk * 64 + tcol + 16 * w;
            if (gid == rowid) sc[cc][w] = -INFINITY;
        }
    }

    __syncthreads();
    #pragma unroll
    for (int cc = 0; cc < 2; cc++) {
        int ci = tcg + 16 * cc;
        float m = sc[cc][0];
        #pragma unroll
        for (int w = 1; w < 4; w++) m = fmaxf(m, sc[cc][w]);
        pr[tcol][ci] = m;
    }
    __syncthreads();
    if (tid < 32) {
        float m = pr[0][tid];
        #pragma unroll
        for (int x = 1; x < 16; x++) m = fmaxf(m, pr[x][tid]);
        Mrow[tid] = m;
    }
    __syncthreads();
    #pragma unroll
    for (int cc = 0; cc < 2; cc++) {
        int ci = tcg + 16 * cc;
        float Mf = Mrow[ci];
        float s = 0.f;
        #pragma unroll
        for (int w = 0; w < 4; w++) s += __expf(sc[cc][w] - Mf);
        pr[tcol][ci] = s;
    }
    __syncthreads();
    if (tid < 32) {
        float s = 0.f;
        #pragma unroll
        for (int x = 0; x < 16; x++) s += pr[x][tid];
        int gi = (b * 32 + tid) * NRSB + blk;
        g_cM[gi] = Mrow[tid];
        g_cS[gi] = s;
    }
}

// ----------------------------------------------------------------------------
// Kernel 6: final exact top-7 among candidates.
// ----------------------------------------------------------------------------
__global__ __launch_bounds__(32) void final_topk() {
    __shared__ float ls[B][32];
    __shared__ float val[NCAND];
    const int tid = threadIdx.x;
    for (int b = 0; b < B; b++) {
        float M = -INFINITY;
        #pragma unroll
        for (int blk = 0; blk < NRSB; blk++)
            M = fmaxf(M, g_cM[(b * 32 + tid) * NRSB + blk]);
        float S = 0.f;
        #pragma unroll
        for (int blk = 0; blk < NRSB; blk++)
            S += g_cS[(b * 32 + tid) * NRSB + blk] *
                 __expf(g_cM[(b * 32 + tid) * NRSB + blk] - M);
        ls[b][tid] = M + logf(S);
    }
    __syncwarp();
    if (tid < NCAND) {
        int t = g_cand[tid];
        float sum = 0.f;
        for (int b = 0; b < B; b++) {
            float tavg = 0.5f * (ls[b][2 * tid] + ls[b][2 * tid + 1]);
            sum += 0.5f * g_instAvg[b * L + t] + 0.5f * tavg - g_d[b * L + t];
        }
        val[tid] = sum * 0.25f;
    }
    __syncwarp();
    if (tid == 0) {
        unsigned used = 0;
        for (int k = 0; k < TOPK; k++) {
            float best = -INFINITY;
            int bc = -1, bt = 1 << 30;
            for (int c = 0; c < NCAND; c++) {
                if ((used >> c) & 1) continue;
                int t = g_cand[c];
                if (val[c] > best || (val[c] == best && t < bt)) {
                    best = val[c]; bc = c; bt = t;
                }
            }
            used |= 1u << bc;
            g_topk[k] = g_cand[bc];
        }
    }
}

// ----------------------------------------------------------------------------
// Kernel 7a: chunk sums for cumsum. Grid (32 chunks, H, B), 64 threads.
// ----------------------------------------------------------------------------
__global__ __launch_bounds__(64) void cumsum_pass1(const float* __restrict__ V) {
    const int chunk = blockIdx.x, h = blockIdx.y, b = blockIdx.z;
    const int e = threadIdx.x;
    const long baseIn = (long)b * L * C + (long)h * E + e;
    const int l0 = chunk * 64;
    float s = 0.f;
    #pragma unroll 8
    for (int i = 0; i < 64; i++) s += V[baseIn + (long)(l0 + i) * C];
    g_csum[((b * H + h) * 32 + chunk) * E + e] = s;
}

// ----------------------------------------------------------------------------
// Kernel 7b: scan each chunk with offset; top-7 rows rescaled.
// ----------------------------------------------------------------------------
__global__ __launch_bounds__(64) void cumsum_pass2(const float* __restrict__ V,
                                                   float* __restrict__ out) {
    const int chunk = blockIdx.x, h = blockIdx.y, b = blockIdx.z;
    const int e = threadIdx.x;
    __shared__ int idx7[TOPK];
    if (threadIdx.x < TOPK) idx7[threadIdx.x] = g_topk[threadIdx.x];
    __syncthreads();

    float off = 0.f;
    for (int c = 0; c < chunk; c++)
        off += g_csum[((b * H + h) * 32 + c) * E + e];

    const long baseIn = (long)b * L * C + (long)h * E + e;
    const long baseOut = ((long)(b * H + h) * L) * E + e;
    const int l0 = chunk * 64;
    float acc = off;
    #pragma unroll 4
    for (int i = 0; i < 64; i++) {
        const int l = l0 + i;
        acc += V[baseIn + (long)l * C];
        float o = acc;
        #pragma unroll
        for (int k = 0; k < TOPK; k++)
            if (l == idx7[k]) o = acc / (float)(l + 1);
        out[baseOut + (long)l * E] = o;
    }
}

// ----------------------------------------------------------------------------
// Launch: side stream runs instance + cumsum_pass1 concurrently with
// convert->temporal; event-join before combine. Streams/events created once
// on the first (non-captured) correctness call.
// ----------------------------------------------------------------------------
extern "C" void kernel_launch(void* const* d_in, const int* in_sizes, int n_in,
                              void* d_out, int out_size) {
    const float* Q = (const float*)d_in[0];
    const float* K = (const float*)d_in[1];
    const float* V = (const float*)d_in[2];
    float* out = (float*)d_out;

    static cudaStream_t s1 = nullptr;
    static cudaEvent_t evFork = nullptr, evJoin = nullptr;
    static bool smemSet = false;
    if (!smemSet) {
        cudaFuncSetAttribute(temporal_mma,
                             cudaFuncAttributeMaxDynamicSharedMemorySize, 65536);
        cudaStreamCreateWithFlags(&s1, cudaStreamNonBlocking);
        cudaEventCreateWithFlags(&evFork, cudaEventDisableTiming);
        cudaEventCreateWithFlags(&evJoin, cudaEventDisableTiming);
        smemSet = true;
    }

    // fork: side stream joins the capture graph
    cudaEventRecord(evFork, 0);
    cudaStreamWaitEvent(s1, evFork, 0);

    // side stream: independent of the bf16 conversion
    instance_kernel<<<L / 4, 128, 0, s1>>>(Q, K);
    cumsum_pass1<<<dim3(32, H, B), 64, 0, s1>>>(V);
    cudaEventRecord(evJoin, s1);

    // main stream
    convert_kernel<<<(B * L2 * C) / 8 / 256, 256>>>(Q, K);
    temporal_mma<<<dim3(NPAIR, B), 128, 65536>>>();
    cudaStreamWaitEvent(0, evJoin, 0);       // need instAvg/d (and pass1) below
    combine_kernel<<<dim3(L / 256, B), 256>>>();
    cand_kernel<<<1, 32>>>();
    rescreen<<<dim3(NRSB, B), 256>>>(Q, K);
    final_topk<<<1, 32>>>();
    cumsum_pass2<<<dim3(32, H, B), 64>>>(V, out);
}

// round 9
// speedup vs baseline: 6.5224x; 1.0574x over previous
#include <cuda_runtime.h>
#include <cuda_bf16.h>
#include <math.h>
#include <stdint.h>

// ----------------------------------------------------------------------------
// Shapes (fixed)
// ----------------------------------------------------------------------------
#define B 4
#define L 2048
#define H 8
#define E 64
#define C 512
#define L2 4096
#define TOPK 7
#define NTILE 32
#define NPAIR 528
#define NCAND 16
#define NRSB 64            // rescreen col-blocks (64 cols each)

// ----------------------------------------------------------------------------
// Device scratch
// ----------------------------------------------------------------------------
__device__ __nv_bfloat16 g_Zbf[(size_t)B * L2 * C];   // 16 MB bf16 Z = concat(q,k)
__device__ float g_Mpart[B * NTILE * L2];
__device__ float g_Spart[B * NTILE * L2];
__device__ float g_instAvg[B * L];
__device__ float g_d[B * L];
__device__ float g_corrPart[B * L];
__device__ int   g_cand[NCAND];
__device__ float g_cM[B * 2 * NCAND * NRSB];
__device__ float g_cS[B * 2 * NCAND * NRSB];
__device__ int   g_topk[TOPK];
__device__ float g_csum[B * H * 32 * E];

// ----------------------------------------------------------------------------
// Helpers
// ----------------------------------------------------------------------------
#define SWZ(o) ((o) ^ (((o) >> 3) & 0x70))

__device__ __forceinline__ uint32_t smem_u32(const void* p) {
    uint32_t a;
    asm("{ .reg .u64 t; cvta.to.shared.u64 t, %1; cvt.u32.u64 %0, t; }"
        : "=r"(a) : "l"(p));
    return a;
}

#define LDSM4(r0, r1, r2, r3, addr)                                             \
    asm volatile("ldmatrix.sync.aligned.m8n8.x4.shared.b16 {%0,%1,%2,%3}, [%4];" \
                 : "=r"(r0), "=r"(r1), "=r"(r2), "=r"(r3) : "r"(addr))

#define MMA16816(c, a, b0v, b1v)                                                \
    asm volatile("mma.sync.aligned.m16n8k16.row.col.f32.bf16.bf16.f32 "         \
                 "{%0,%1,%2,%3},{%4,%5,%6,%7},{%8,%9},{%0,%1,%2,%3};"           \
                 : "+f"((c)[0]), "+f"((c)[1]), "+f"((c)[2]), "+f"((c)[3])       \
                 : "r"((a)[0]), "r"((a)[1]), "r"((a)[2]), "r"((a)[3]),          \
                   "r"(b0v), "r"(b1v))

#define CPASYNC16(dst, src)                                                     \
    asm volatile("cp.async.cg.shared.global [%0], [%1], 16;"                    \
                 :: "r"(dst), "l"(src) : "memory")
#define CPCOMMIT() asm volatile("cp.async.commit_group;" ::: "memory")
#define CPWAIT(n)  asm volatile("cp.async.wait_group %0;" :: "n"(n) : "memory")

// upper-triangle index for 8x8 symmetric gram: i<=j
#define TRI(i, j) ((i) * (15 - (i)) / 2 + (j))

// ----------------------------------------------------------------------------
// Kernel 0: convert Q,K fp32 -> bf16 Z (rows: q then k, per batch)
// ----------------------------------------------------------------------------
__global__ __launch_bounds__(256) void convert_kernel(const float* __restrict__ Q,
                                                      const float* __restrict__ K) {
    long t = (long)blockIdx.x * 256 + threadIdx.x;
    long e = t * 8;
    int b = (int)(e / ((long)L2 * C));
    long r = e % ((long)L2 * C);
    int row = (int)(r / C);
    int k = (int)(r % C);
    const float* src = (row < L) ? Q + ((long)b * L + row) * C + k
                                 : K + ((long)b * L + (row - L)) * C + k;
    float4 f0 = *(const float4*)(src);
    float4 f1 = *(const float4*)(src + 4);
    __nv_bfloat162 h0 = __float22bfloat162_rn(make_float2(f0.x, f0.y));
    __nv_bfloat162 h1 = __float22bfloat162_rn(make_float2(f0.z, f0.w));
    __nv_bfloat162 h2 = __float22bfloat162_rn(make_float2(f1.x, f1.y));
    __nv_bfloat162 h3 = __float22bfloat162_rn(make_float2(f1.z, f1.w));
    uint4 o;
    o.x = *(uint32_t*)&h0; o.y = *(uint32_t*)&h1;
    o.z = *(uint32_t*)&h2; o.w = *(uint32_t*)&h3;
    *(uint4*)(g_Zbf + e) = o;
}

// ----------------------------------------------------------------------------
// Kernel 1: instance-CL, warp-per-t, register accumulators.
// ----------------------------------------------------------------------------
__global__ __launch_bounds__(128) void instance_kernel(const float* __restrict__ Q,
                                                       const float* __restrict__ K) {
    const int wid = threadIdx.x >> 5, ln = threadIdx.x & 31;
    const int t = blockIdx.x * 4 + wid;

    float acc[36];
    #pragma unroll
    for (int p = 0; p < 36; p++) acc[p] = 0.f;

    #pragma unroll 2
    for (int ck = 0; ck < 16; ck++) {
        const int c = ck * 32 + ln;
        float z[8];
        #pragma unroll
        for (int v = 0; v < 4; v++) z[v] = __ldg(Q + ((size_t)v * L + t) * C + c);
        #pragma unroll
        for (int v = 0; v < 4; v++) z[4 + v] = __ldg(K + ((size_t)v * L + t) * C + c);
        int p = 0;
        #pragma unroll
        for (int i = 0; i < 8; i++)
            #pragma unroll
            for (int j = i; j < 8; j++) { acc[p] = fmaf(z[i], z[j], acc[p]); p++; }
    }

    #pragma unroll
    for (int p = 0; p < 36; p++) {
        #pragma unroll
        for (int o = 16; o > 0; o >>= 1)
            acc[p] += __shfl_xor_sync(0xffffffffu, acc[p], o);
    }

    float lse[8];
    #pragma unroll
    for (int r = 0; r < 8; r++) {
        float m = -INFINITY;
        #pragma unroll
        for (int j = 0; j < 8; j++) {
            if (j == r) continue;
            float g = (j < r) ? acc[TRI(j, r)] : acc[TRI(r, j)];
            m = fmaxf(m, g);
        }
        float s = 0.f;
        #pragma unroll
        for (int j = 0; j < 8; j++) {
            if (j == r) continue;
            float g = (j < r) ? acc[TRI(j, r)] : acc[TRI(r, j)];
            s += __expf(g - m);
        }
        lse[r] = m + logf(s);
    }

    if (ln < 4) {
        g_instAvg[ln * L + t] = 0.5f * (lse[ln] + lse[ln + 4]);
        g_d[ln * L + t] = acc[TRI(ln, ln + 4)];
    }
}

// ----------------------------------------------------------------------------
// Kernel 2: symmetric temporal gram, mma.sync bf16, 64x32 warp tile.
// 256 threads = 8 warps in 2x4 (wr row-half, wc col-quadrant) -> 128x128 CTA.
// Per warp per ks: 6 LDSM (A:4, B:2) feed 16 MMA16816 -> tensor-bound with
// ~115 regs/thread -> 2 CTAs/SM = 16 warps for latency hiding.
// ----------------------------------------------------------------------------
__global__ __launch_bounds__(256, 2) void temporal_mma() {
    int p = blockIdx.x;
    int i = 0;
    while (p >= NTILE - i) { p -= NTILE - i; i++; }
    const int j = i + p;
    const int b = blockIdx.y;

    extern __shared__ __align__(1024) char dsm[];
    const uint32_t aBase = smem_u32(dsm);            // As[2]: 32 KB
    const uint32_t bBase = aBase + 32768;            // Bs[2]: 32 KB
    float* rmW = (float*)dsm;                        // reuse post-mainloop
    float* smW = rmW + 512;                          // [4][128]
    float* cmW = smW + 512;                          // [2][128]
    float* csW = cmW + 256;                          // [2][128]

    const int tid = threadIdx.x;
    const int ln = tid & 31;
    const int wr = (tid >> 5) >> 2;                  // 0..1 (64-row half)
    const int wc = (tid >> 5) & 3;                   // 0..3 (32-col quadrant)
    const int qr = ln >> 2, qc = ln & 3;

    const __nv_bfloat16* Zb = g_Zbf + (size_t)b * L2 * C;
    const __nv_bfloat16* Arows = Zb + (size_t)i * 128 * C;
    const __nv_bfloat16* Brows = Zb + (size_t)j * 128 * C;

    // cp.async per-thread slots: 4 units per array per chunk (256 threads)
    const int ldSeg = tid & 7;
    const int ldRow[4] = {(tid + 0) >> 3, (tid + 256) >> 3,
                          (tid + 512) >> 3, (tid + 768) >> 3};
    const uint32_t ldOff[4] = {
        (uint32_t)SWZ(ldRow[0] * 128 + ldSeg * 16),
        (uint32_t)SWZ(ldRow[1] * 128 + ldSeg * 16),
        (uint32_t)SWZ(ldRow[2] * 128 + ldSeg * 16),
        (uint32_t)SWZ(ldRow[3] * 128 + ldSeg * 16)};

    const int blk = ln >> 3, r8 = ln & 7;

    // swizzle-free LDSM bases (mask invariant as row += 16)
    const int rowA0 = wr * 64 + (blk & 1) * 8 + r8;          // mt adds +16
    const int maskA = (rowA0 * 16) & 0x70;
    const uint32_t pA = (uint32_t)(maskA >> 5);
    const uint32_t cA0 = rowA0 * 128 + ((((blk >> 1) << 4)) ^ (maskA & 0x10));

    const int rowB0 = wc * 32 + (blk >> 1) * 8 + r8;         // nn adds +16
    const int maskB = (rowB0 * 16) & 0x70;
    const uint32_t pB = (uint32_t)(maskB >> 5);
    const uint32_t cB0 = rowB0 * 128 + ((((blk & 1) << 4)) ^ (maskB & 0x10));

    float acc[4][4][4];            // [mt 16-row][nt 8-col][quad]
    #pragma unroll
    for (int mt = 0; mt < 4; mt++)
        #pragma unroll
        for (int nt = 0; nt < 4; nt++)
            #pragma unroll
            for (int q = 0; q < 4; q++) acc[mt][nt][q] = 0.f;

    // prefetch chunk 0
    {
        #pragma unroll
        for (int u = 0; u < 4; u++) {
            CPASYNC16(aBase + ldOff[u], Arows + (size_t)ldRow[u] * C + ldSeg * 8);
            CPASYNC16(bBase + ldOff[u], Brows + (size_t)ldRow[u] * C + ldSeg * 8);
        }
        CPCOMMIT();
    }

    #pragma unroll 1
    for (int ck = 0; ck < 8; ck++) {
        if (ck < 7) {
            const uint32_t abuf = aBase + ((ck + 1) & 1) * 16384;
            const uint32_t bbuf = bBase + ((ck + 1) & 1) * 16384;
            const int co = (ck + 1) * 64;
            #pragma unroll
            for (int u = 0; u < 4; u++) {
                CPASYNC16(abuf + ldOff[u], Arows + (size_t)ldRow[u] * C + co + ldSeg * 8);
                CPASYNC16(bbuf + ldOff[u], Brows + (size_t)ldRow[u] * C + co + ldSeg * 8);
            }
            CPCOMMIT();
            CPWAIT(1);
        } else {
            CPWAIT(0);
        }
        __syncthreads();

        const uint32_t abA = aBase + (ck & 1) * 16384;
        const uint32_t bbB = bBase + (ck & 1) * 16384;
        #pragma unroll
        for (uint32_t ks = 0; ks < 4; ks++) {
            const uint32_t offA = ((ks ^ pA) << 5);
            const uint32_t offB = ((ks ^ pB) << 5);
            uint32_t af[4][4];
            #pragma unroll
            for (int mt = 0; mt < 4; mt++)
                LDSM4(af[mt][0], af[mt][1], af[mt][2], af[mt][3],
                      abA + cA0 + mt * (16 * 128) + offA);
            #pragma unroll
            for (int nn = 0; nn < 2; nn++) {
                uint32_t bf0, bf1, bf2, bf3;
                LDSM4(bf0, bf1, bf2, bf3, bbB + cB0 + nn * (16 * 128) + offB);
                #pragma unroll
                for (int mt = 0; mt < 4; mt++) {
                    MMA16816(acc[mt][2 * nn], af[mt], bf0, bf1);
                    MMA16816(acc[mt][2 * nn + 1], af[mt], bf2, bf3);
                }
            }
        }
        __syncthreads();
    }

    // diagonal exclusion (only diag tile)
    if (i == j) {
        #pragma unroll
        for (int mt = 0; mt < 4; mt++)
            #pragma unroll
            for (int nt = 0; nt < 4; nt++)
                #pragma unroll
                for (int h = 0; h < 2; h++)
                    #pragma unroll
                    for (int q = 0; q < 2; q++) {
                        int rI = wr * 64 + mt * 16 + h * 8 + qr;
                        int cI = wc * 32 + nt * 8 + qc * 2 + q;
                        if (rI == cI) acc[mt][nt][h * 2 + q] = -INFINITY;
                    }
    }

    // ---- row-side LSE partials (slot j): 4 col-quadrant partials ----
    #pragma unroll
    for (int mt = 0; mt < 4; mt++)
        #pragma unroll
        for (int h = 0; h < 2; h++) {
            float m = -INFINITY;
            #pragma unroll
            for (int nt = 0; nt < 4; nt++)
                m = fmaxf(m, fmaxf(acc[mt][nt][h * 2], acc[mt][nt][h * 2 + 1]));
            m = fmaxf(m, __shfl_xor_sync(0xffffffffu, m, 1));
            m = fmaxf(m, __shfl_xor_sync(0xffffffffu, m, 2));
            if (qc == 0) rmW[wc * 128 + wr * 64 + mt * 16 + h * 8 + qr] = m;
        }
    __syncthreads();
    #pragma unroll
    for (int mt = 0; mt < 4; mt++)
        #pragma unroll
        for (int h = 0; h < 2; h++) {
            int r = wr * 64 + mt * 16 + h * 8 + qr;
            float Mf = fmaxf(fmaxf(rmW[r], rmW[128 + r]),
                             fmaxf(rmW[256 + r], rmW[384 + r]));
            float thr = Mf - 17.0f;
            float s = 0.f;
            #pragma unroll
            for (int nt = 0; nt < 4; nt++)
                #pragma unroll
                for (int q = 0; q < 2; q++) {
                    float v = acc[mt][nt][h * 2 + q];
                    if (v > thr) s += __expf(v - Mf);
                }
            s += __shfl_xor_sync(0xffffffffu, s, 1);
            s += __shfl_xor_sync(0xffffffffu, s, 2);
            if (qc == 0) smW[wc * 128 + r] = s;
        }
    __syncthreads();
    if (tid < 128) {
        float Mf = fmaxf(fmaxf(rmW[tid], rmW[128 + tid]),
                         fmaxf(rmW[256 + tid], rmW[384 + tid]));
        float S = smW[tid] + smW[128 + tid] + smW[256 + tid] + smW[384 + tid];
        int gi = (b * NTILE + j) * L2 + i * 128 + tid;
        g_Mpart[gi] = Mf;
        g_Spart[gi] = S;
    }

    // ---- col-side LSE partials (slot i), only off-diagonal ----
    if (i != j) {
        #pragma unroll
        for (int nt = 0; nt < 4; nt++)
            #pragma unroll
            for (int q = 0; q < 2; q++) {
                float m = -INFINITY;
                #pragma unroll
                for (int mt = 0; mt < 4; mt++)
                    #pragma unroll
                    for (int h = 0; h < 2; h++)
                        m = fmaxf(m, acc[mt][nt][h * 2 + q]);
                m = fmaxf(m, __shfl_xor_sync(0xffffffffu, m, 4));
                m = fmaxf(m, __shfl_xor_sync(0xffffffffu, m, 8));
                m = fmaxf(m, __shfl_xor_sync(0xffffffffu, m, 16));
                if (qr == 0) cmW[wr * 128 + wc * 32 + nt * 8 + qc * 2 + q] = m;
            }
        __syncthreads();
        #pragma unroll
        for (int nt = 0; nt < 4; nt++)
            #pragma unroll
            for (int q = 0; q < 2; q++) {
                int cI = wc * 32 + nt * 8 + qc * 2 + q;
                float Mf = fmaxf(cmW[cI], cmW[128 + cI]);
                float thr = Mf - 17.0f;
                float s = 0.f;
                #pragma unroll
                for (int mt = 0; mt < 4; mt++)
                    #pragma unroll
                    for (int h = 0; h < 2; h++) {
                        float v = acc[mt][nt][h * 2 + q];
                        if (v > thr) s += __expf(v - Mf);
                    }
                s += __shfl_xor_sync(0xffffffffu, s, 4);
                s += __shfl_xor_sync(0xffffffffu, s, 8);
                s += __shfl_xor_sync(0xffffffffu, s, 16);
                if (qr == 0) csW[wr * 128 + cI] = s;
            }
        __syncthreads();
        if (tid < 128) {
            float Mf = fmaxf(cmW[tid], cmW[128 + tid]);
            float S = csW[tid] + csW[128 + tid];
            int gi = (b * NTILE + i) * L2 + j * 128 + tid;
            g_Mpart[gi] = Mf;
            g_Spart[gi] = S;
        }
    }
}

// ----------------------------------------------------------------------------
// Kernel 3: combine 32 partials per row for one batch -> corrPart[b][t]
// ----------------------------------------------------------------------------
__global__ void combine_kernel() {
    int t = blockIdx.x * blockDim.x + threadIdx.x;
    int b = blockIdx.y;
    if (t >= L) return;
    float lse[2];
    #pragma unroll
    for (int hh = 0; hh < 2; hh++) {
        const int row = t + hh * L;
        float M = -INFINITY;
        #pragma unroll
        for (int ct = 0; ct < NTILE; ct++)
            M = fmaxf(M, g_Mpart[(b * NTILE + ct) * L2 + row]);
        float S = 0.f;
        #pragma unroll
        for (int ct = 0; ct < NTILE; ct++)
            S += g_Spart[(b * NTILE + ct) * L2 + row] *
                 __expf(g_Mpart[(b * NTILE + ct) * L2 + row] - M);
        lse[hh] = M + logf(S);
    }
    const float tAvg = 0.5f * (lse[0] + lse[1]);
    g_corrPart[b * L + t] =
        0.5f * g_instAvg[b * L + t] + 0.5f * tAvg - g_d[b * L + t];
}

// ----------------------------------------------------------------------------
// Kernel 4: top-NCAND candidate extraction (single warp).
// ----------------------------------------------------------------------------
__global__ __launch_bounds__(32) void cand_kernel() {
    const int ln = threadIdx.x;
    float v[64];
    #pragma unroll
    for (int u = 0; u < 64; u++) {
        int idx = u * 32 + ln;
        v[u] = g_corrPart[idx] + g_corrPart[L + idx] +
               g_corrPart[2 * L + idx] + g_corrPart[3 * L + idx];
    }
    float pv = INFINITY;
    int pi = -1;
    for (int r = 0; r < NCAND; r++) {
        float bv = -INFINITY;
        int bi = 1 << 30;
        #pragma unroll
        for (int u = 0; u < 64; u++) {
            int idx = u * 32 + ln;
            bool lt = (v[u] < pv) || (v[u] == pv && idx > pi);
            if (lt && (v[u] > bv || (v[u] == bv && idx < bi))) { bv = v[u]; bi = idx; }
        }
        #pragma unroll
        for (int o = 16; o > 0; o >>= 1) {
            float ov = __shfl_xor_sync(0xffffffffu, bv, o);
            int oi = __shfl_xor_sync(0xffffffffu, bi, o);
            if (ov > bv || (ov == bv && oi < bi)) { bv = ov; bi = oi; }
        }
        if (ln == 0) g_cand[r] = bi;
        pv = bv; pi = bi;
    }
}

// ----------------------------------------------------------------------------
// Kernel 5: exact fp32 rescreen of NCAND candidates. Grid (NRSB=64, B).
// ----------------------------------------------------------------------------
__global__ __launch_bounds__(256) void rescreen(const float* __restrict__ Q,
                                                const float* __restrict__ K) {
    const int blk = blockIdx.x, b = blockIdx.y;
    __shared__ float czT[32][32];
    __shared__ float colT[32][64];
    __shared__ float pr[16][32];
    __shared__ float Mrow[32];
    __shared__ int cand[NCAND];

    const int tid = threadIdx.x;
    const int tcg = tid >> 4, tcol = tid & 15;
    if (tid < NCAND) cand[tid] = g_cand[tid];
    __syncthreads();

    float sc[2][4];
    #pragma unroll
    for (int cc = 0; cc < 2; cc++)
        #pragma unroll
        for (int w = 0; w < 4; w++) sc[cc][w] = 0.f;

    for (int ck = 0; ck < 16; ck++) {
        __syncthreads();
        for (int idx = tid; idx < 32 * 32; idx += 256) {
            int r = idx >> 5, kk = idx & 31;
            int c = r >> 1, h = r & 1;
            int t = cand[c];
            const float* src = h ? (K + ((size_t)b * L + t) * C)
                                 : (Q + ((size_t)b * L + t) * C);
            czT[kk][r] = src[ck * 32 + kk];
        }
        for (int idx = tid; idx < 64 * 32; idx += 256) {
            int r = idx >> 5, kk = idx & 31;
            int gid = blk * 64 + r;
            const float* src = (gid < L) ? (Q + ((size_t)b * L + gid) * C)
                                         : (K + ((size_t)b * L + gid - L) * C);
            colT[kk][r] = src[ck * 32 + kk];
        }
        __syncthreads();
        #pragma unroll 4
        for (int kk = 0; kk < 32; kk++) {
            float a0 = czT[kk][tcg], a1 = czT[kk][tcg + 16];
            float bv[4];
            #pragma unroll
            for (int w = 0; w < 4; w++) bv[w] = colT[kk][tcol + 16 * w];
            #pragma unroll
            for (int w = 0; w < 4; w++) {
                sc[0][w] = fmaf(a0, bv[w], sc[0][w]);
                sc[1][w] = fmaf(a1, bv[w], sc[1][w]);
            }
        }
    }

    #pragma unroll
    for (int cc = 0; cc < 2; cc++) {
        int ci = tcg + 16 * cc;
        int rowid = cand[ci >> 1] + (ci & 1) * L;
        #pragma unroll
        for (int w = 0; w < 4; w++) {
            int gid = blk * 64 + tcol + 16 * w;
            if (gid == rowid) sc[cc][w] = -INFINITY;
        }
    }

    __syncthreads();
    #pragma unroll
    for (int cc = 0; cc < 2; cc++) {
        int ci = tcg + 16 * cc;
        float m = sc[cc][0];
        #pragma unroll
        for (int w = 1; w < 4; w++) m = fmaxf(m, sc[cc][w]);
        pr[tcol][ci] = m;
    }
    __syncthreads();
    if (tid < 32) {
        float m = pr[0][tid];
        #pragma unroll
        for (int x = 1; x < 16; x++) m = fmaxf(m, pr[x][tid]);
        Mrow[tid] = m;
    }
    __syncthreads();
    #pragma unroll
    for (int cc = 0; cc < 2; cc++) {
        int ci = tcg + 16 * cc;
        float Mf = Mrow[ci];
        float s = 0.f;
        #pragma unroll
        for (int w = 0; w < 4; w++) s += __expf(sc[cc][w] - Mf);
        pr[tcol][ci] = s;
    }
    __syncthreads();
    if (tid < 32) {
        float s = 0.f;
        #pragma unroll
        for (int x = 0; x < 16; x++) s += pr[x][tid];
        int gi = (b * 32 + tid) * NRSB + blk;
        g_cM[gi] = Mrow[tid];
        g_cS[gi] = s;
    }
}

// ----------------------------------------------------------------------------
// Kernel 6: final exact top-7 among candidates.
// ----------------------------------------------------------------------------
__global__ __launch_bounds__(32) void final_topk() {
    __shared__ float ls[B][32];
    __shared__ float val[NCAND];
    const int tid = threadIdx.x;
    for (int b = 0; b < B; b++) {
        float M = -INFINITY;
        #pragma unroll
        for (int blk = 0; blk < NRSB; blk++)
            M = fmaxf(M, g_cM[(b * 32 + tid) * NRSB + blk]);
        float S = 0.f;
        #pragma unroll
        for (int blk = 0; blk < NRSB; blk++)
            S += g_cS[(b * 32 + tid) * NRSB + blk] *
                 __expf(g_cM[(b * 32 + tid) * NRSB + blk] - M);
        ls[b][tid] = M + logf(S);
    }
    __syncwarp();
    if (tid < NCAND) {
        int t = g_cand[tid];
        float sum = 0.f;
        for (int b = 0; b < B; b++) {
            float tavg = 0.5f * (ls[b][2 * tid] + ls[b][2 * tid + 1]);
            sum += 0.5f * g_instAvg[b * L + t] + 0.5f * tavg - g_d[b * L + t];
        }
        val[tid] = sum * 0.25f;
    }
    __syncwarp();
    if (tid == 0) {
        unsigned used = 0;
        for (int k = 0; k < TOPK; k++) {
            float best = -INFINITY;
            int bc = -1, bt = 1 << 30;
            for (int c = 0; c < NCAND; c++) {
                if ((used >> c) & 1) continue;
                int t = g_cand[c];
                if (val[c] > best || (val[c] == best && t < bt)) {
                    best = val[c]; bc = c; bt = t;
                }
            }
            used |= 1u << bc;
            g_topk[k] = g_cand[bc];
        }
    }
}

// ----------------------------------------------------------------------------
// Kernel 7a: chunk sums for cumsum. Grid (32 chunks, H, B), 64 threads.
// ----------------------------------------------------------------------------
__global__ __launch_bounds__(64) void cumsum_pass1(const float* __restrict__ V) {
    const int chunk = blockIdx.x, h = blockIdx.y, b = blockIdx.z;
    const int e = threadIdx.x;
    const long baseIn = (long)b * L * C + (long)h * E + e;
    const int l0 = chunk * 64;
    float s = 0.f;
    #pragma unroll 8
    for (int i = 0; i < 64; i++) s += V[baseIn + (long)(l0 + i) * C];
    g_csum[((b * H + h) * 32 + chunk) * E + e] = s;
}

// ----------------------------------------------------------------------------
// Kernel 7b: scan each chunk with offset; top-7 rows rescaled.
// ----------------------------------------------------------------------------
__global__ __launch_bounds__(64) void cumsum_pass2(const float* __restrict__ V,
                                                   float* __restrict__ out) {
    const int chunk = blockIdx.x, h = blockIdx.y, b = blockIdx.z;
    const int e = threadIdx.x;
    __shared__ int idx7[TOPK];
    if (threadIdx.x < TOPK) idx7[threadIdx.x] = g_topk[threadIdx.x];
    __syncthreads();

    float off = 0.f;
    for (int c = 0; c < chunk; c++)
        off += g_csum[((b * H + h) * 32 + c) * E + e];

    const long baseIn = (long)b * L * C + (long)h * E + e;
    const long baseOut = ((long)(b * H + h) * L) * E + e;
    const int l0 = chunk * 64;
    float acc = off;
    #pragma unroll 4
    for (int i = 0; i < 64; i++) {
        const int l = l0 + i;
        acc += V[baseIn + (long)l * C];
        float o = acc;
        #pragma unroll
        for (int k = 0; k < TOPK; k++)
            if (l == idx7[k]) o = acc / (float)(l + 1);
        out[baseOut + (long)l * E] = o;
    }
}

// ----------------------------------------------------------------------------
// Launch: side stream runs instance + cumsum_pass1 concurrently with
// convert->temporal; event-join before combine.
// ----------------------------------------------------------------------------
extern "C" void kernel_launch(void* const* d_in, const int* in_sizes, int n_in,
                              void* d_out, int out_size) {
    const float* Q = (const float*)d_in[0];
    const float* K = (const float*)d_in[1];
    const float* V = (const float*)d_in[2];
    float* out = (float*)d_out;

    static cudaStream_t s1 = nullptr;
    static cudaEvent_t evFork = nullptr, evJoin = nullptr;
    static bool smemSet = false;
    if (!smemSet) {
        cudaFuncSetAttribute(temporal_mma,
                             cudaFuncAttributeMaxDynamicSharedMemorySize, 65536);
        cudaStreamCreateWithFlags(&s1, cudaStreamNonBlocking);
        cudaEventCreateWithFlags(&evFork, cudaEventDisableTiming);
        cudaEventCreateWithFlags(&evJoin, cudaEventDisableTiming);
        smemSet = true;
    }

    // fork: side stream joins the capture graph
    cudaEventRecord(evFork, 0);
    cudaStreamWaitEvent(s1, evFork, 0);

    // side stream: independent of the bf16 conversion
    instance_kernel<<<L / 4, 128, 0, s1>>>(Q, K);
    cumsum_pass1<<<dim3(32, H, B), 64, 0, s1>>>(V);
    cudaEventRecord(evJoin, s1);

    // main stream
    convert_kernel<<<(B * L2 * C) / 8 / 256, 256>>>(Q, K);
    temporal_mma<<<dim3(NPAIR, B), 256, 65536>>>();
    cudaStreamWaitEvent(0, evJoin, 0);       // need instAvg/d (and pass1) below
    combine_kernel<<<dim3(L / 256, B), 256>>>();
    cand_kernel<<<1, 32>>>();
    rescreen<<<dim3(NRSB, B), 256>>>(Q, K);
    final_topk<<<1, 32>>>();
    cumsum_pass2<<<dim3(32, H, B), 64>>>(V, out);
}